// round 9
// baseline (speedup 1.0000x reference)
#include <cuda_runtime.h>
#include <cstdint>

// ---------------- Problem constants ----------------
#define NA   20001
#define FD   133
#define KNB  6
#define HD   1100
#define FHD  700
#define NM   800
#define FFK  1400

// K paddings in PAIRS (bf16x2). Multiples of 16 pairs = 32 elems (one stage).
#define JP_FA   80      // si : T=5
#define JP_X    144     // vi : T=9
#define JP_H    560     // hs/hv : T=35
#define JP_OS   624     // os : T=39
#define JP_OV   1104    // ov : T=69
#define JP_FF   704     // ffn : T=44

// ---------------- Scratch (device globals) ----------------
__device__ __align__(16) uint2 g_fa_p  [(size_t)NA * JP_FA];
__device__ __align__(16) uint2 g_X_p   [(size_t)NA * 3 * JP_X];
__device__ __align__(16) uint2 g_sagg_p[(size_t)NA * JP_H];
__device__ __align__(16) uint2 g_vagg_p[(size_t)NA * 3 * JP_H];
__device__ __align__(16) uint2 g_osin_p[(size_t)NA * JP_OS];
__device__ __align__(16) uint2 g_ovin_p[(size_t)NA * 3 * JP_OV];
__device__ __align__(16) uint2 g_mol_p [(size_t)NM * JP_FF];

__device__ __align__(16) uint2 g_Wis_p [(size_t)JP_FA * HD];
__device__ __align__(16) uint2 g_Wiv_p [(size_t)JP_X  * HD];
__device__ __align__(16) uint2 g_Whs_p [(size_t)JP_H  * HD];
__device__ __align__(16) uint2 g_Whv_p [(size_t)JP_H  * HD];
__device__ __align__(16) uint2 g_Wos_p [(size_t)JP_OS * FHD];
__device__ __align__(16) uint2 g_Wov_p [(size_t)JP_OV * FHD];
__device__ __align__(16) uint2 g_Wff_p [(size_t)JP_FF * FHD];

__device__ __align__(16) float g_si [(size_t)NA * HD];
__device__ __align__(16) float g_s  [(size_t)NA * HD];
__device__ __align__(16) float g_vi [(size_t)NA * 3 * HD];
__device__ __align__(16) float g_v  [(size_t)NA * 3 * HD];
__device__ __align__(16) float g_osb[(size_t)NA * FHD];
__device__ __align__(16) float g_ovb[(size_t)NA * 3 * FHD];
__device__ __align__(16) float g_o  [(size_t)NA * FFK];
__device__ __align__(16) float g_h  [NM * FHD];
__device__ int g_molstart[NM + 1];

// ---------------- bf16 split-pack helper ----------------
__device__ __forceinline__ uint2 splitpack(float x0, float x1) {
    unsigned h;
    asm("cvt.rn.bf16x2.f32 %0, %1, %2;" : "=r"(h) : "f"(x1), "f"(x0));
    float h0 = __uint_as_float(h << 16);
    float h1 = __uint_as_float(h & 0xFFFF0000u);
    unsigned l;
    asm("cvt.rn.bf16x2.f32 %0, %1, %2;" : "=r"(l) : "f"(x1 - h1), "f"(x0 - h0));
    return make_uint2(h, l);
}

__device__ __forceinline__ void cp16(void* dst_smem, const void* src, int bytes) {
    unsigned sa = (unsigned)__cvta_generic_to_shared(dst_smem);
    asm volatile("cp.async.ca.shared.global [%0], [%1], 16, %2;\n"
                 :: "r"(sa), "l"(src), "r"(bytes));
}

#define MMA_BF16(ACC, AF, BF)                                                   \
    asm volatile(                                                               \
        "mma.sync.aligned.m16n8k16.row.col.f32.bf16.bf16.f32 "                  \
        "{%0,%1,%2,%3}, {%4,%5,%6,%7}, {%8,%9}, {%0,%1,%2,%3};\n"               \
        : "+f"(ACC[0]), "+f"(ACC[1]), "+f"(ACC[2]), "+f"(ACC[3])                \
        : "r"(AF[0]), "r"(AF[1]), "r"(AF[2]), "r"(AF[3]),                       \
          "r"(BF[0]), "r"(BF[1]))

// ---------------- bf16x3 GEMM, BK=32 elems/stage, 3-stage ring, 1 sync/stage ----------------
#define ASTP 18
#define BSTP 132
#define STG_A (128 * ASTP)            // uint2
#define STG_B (16 * BSTP)             // uint2
#define STG_U2 (STG_A + STG_B)        // 4416 uint2 = 35328 B
#define SMEM_GEMM (3 * STG_U2 * 8)    // 105984 B

template<bool RELU, bool HAS_ADD, bool HAS_BIAS, bool WRITE_RAW>
__global__ __launch_bounds__(256, 2)
void bgemm_kernel(const uint2* __restrict__ A, const uint2* __restrict__ B,
                  const float* __restrict__ Add, const float* __restrict__ bias,
                  float* __restrict__ C, float* __restrict__ Craw,
                  int M, int N, int T, int ldp)
{
    extern __shared__ __align__(16) uint2 smem_u2[];

    const int tid = threadIdx.x;
    const int rowBase = blockIdx.y * 128;
    const int colBase = blockIdx.x * 128;
    const int warpId = tid >> 5;
    const int lane = tid & 31;
    const int g  = lane >> 2;
    const int tg = lane & 3;
    const int wm = (warpId & 1) * 64;
    const int wn = (warpId >> 1) * 32;

    float acc[4][4][4];
    #pragma unroll
    for (int mi = 0; mi < 4; mi++)
        #pragma unroll
        for (int ni = 0; ni < 4; ni++)
            #pragma unroll
            for (int j = 0; j < 4; j++) acc[mi][ni][j] = 0.f;

    auto load_stage = [&](int t, int st) {
        uint2* As = smem_u2 + st * STG_U2;
        uint2* Bs = As + STG_A;
        #pragma unroll
        for (int i = 0; i < 4; i++) {        // A: 1024 chunks (16B = 2 pairs)
            int c = tid + i * 256;
            int m = c >> 3, q = c & 7;
            int gm = rowBase + m;
            bool ok = gm < M;
            const uint2* src = ok ? (A + (size_t)gm * ldp + t * 16 + q * 2) : A;
            cp16(&As[m * ASTP + q * 2], src, ok ? 16 : 0);
        }
        #pragma unroll
        for (int i = 0; i < 4; i++) {        // B: 1024 chunks (2 cols)
            int c = tid + i * 256;
            int j = c >> 6, q = c & 63;
            int gn = colBase + q * 2;
            bool ok = gn < N;
            const uint2* src = ok ? (B + (size_t)(t * 16 + j) * N + gn) : B;
            cp16(&Bs[j * BSTP + q * 2], src, ok ? 16 : 0);
        }
        asm volatile("cp.async.commit_group;\n");
    };

    load_stage(0, 0);
    if (T > 1) load_stage(1, 1);

    for (int t = 0; t < T; t++) {
        // stage-t data must be complete; one younger group may stay pending
        if (t + 1 < T) asm volatile("cp.async.wait_group 1;\n");
        else           asm volatile("cp.async.wait_group 0;\n");
        __syncthreads();   // stage-t data visible to all warps; all warps done with stage t-1

        // refill buffer (t+2)%3 == (t-1)%3 (its compute finished at t-1, guarded by sync above)
        if (t + 2 < T) load_stage(t + 2, (t + 2) % 3);

        const uint2* As = smem_u2 + (t % 3) * STG_U2;
        const uint2* Bs = As + STG_A;

        #pragma unroll
        for (int ks = 0; ks < 2; ks++) {
            const int kb = ks * 8;
            unsigned ah[4][4], al[4][4], bh[4][2], bl[4][2];
            #pragma unroll
            for (int mi = 0; mi < 4; mi++) {
                int r = wm + mi * 16 + g;
                uint2 p0 = As[r * ASTP + kb + tg];
                uint2 p1 = As[(r + 8) * ASTP + kb + tg];
                uint2 p2 = As[r * ASTP + kb + 4 + tg];
                uint2 p3 = As[(r + 8) * ASTP + kb + 4 + tg];
                ah[mi][0] = p0.x; ah[mi][1] = p1.x; ah[mi][2] = p2.x; ah[mi][3] = p3.x;
                al[mi][0] = p0.y; al[mi][1] = p1.y; al[mi][2] = p2.y; al[mi][3] = p3.y;
            }
            #pragma unroll
            for (int ni = 0; ni < 4; ni++) {
                int n = wn + ni * 8 + g;
                uint2 q0 = Bs[(kb + tg) * BSTP + n];
                uint2 q1 = Bs[(kb + 4 + tg) * BSTP + n];
                bh[ni][0] = q0.x; bh[ni][1] = q1.x;
                bl[ni][0] = q0.y; bl[ni][1] = q1.y;
            }
            #pragma unroll
            for (int mi = 0; mi < 4; mi++)
                #pragma unroll
                for (int ni = 0; ni < 4; ni++) {
                    MMA_BF16(acc[mi][ni], ah[mi], bl[ni]);   // hi*lo
                    MMA_BF16(acc[mi][ni], al[mi], bh[ni]);   // lo*hi
                    MMA_BF16(acc[mi][ni], ah[mi], bh[ni]);   // hi*hi last
                }
        }
    }

    #pragma unroll
    for (int mi = 0; mi < 4; mi++) {
        int r0 = rowBase + wm + mi * 16 + g;
        #pragma unroll
        for (int ni = 0; ni < 4; ni++) {
            int cN = colBase + wn + ni * 8 + tg * 2;
            if (cN >= N) continue;
            #pragma unroll
            for (int half = 0; half < 2; half++) {
                int r = r0 + half * 8;
                if (r >= M) continue;
                size_t idx = (size_t)r * N + cN;
                float2 vv;
                vv.x = acc[mi][ni][half * 2 + 0];
                vv.y = acc[mi][ni][half * 2 + 1];
                if (HAS_ADD) {
                    float2 a = *(const float2*)(Add + idx);
                    vv.x += a.x; vv.y += a.y;
                }
                if (HAS_BIAS) {
                    float2 b = *(const float2*)(bias + cN);
                    vv.x += b.x; vv.y += b.y;
                }
                if (WRITE_RAW) *(float2*)(Craw + idx) = vv;
                if (RELU) { vv.x = fmaxf(vv.x, 0.f); vv.y = fmaxf(vv.y, 0.f); }
                *(float2*)(C + idx) = vv;
            }
        }
    }
}

// ---------------- weight split-pack (2-segment k remap), layout [j][n] ----------------
__global__ void packW_kernel(const float* __restrict__ W, int N, int Jtot,
                             int s0, int l0, int d0, int s1, int l1, int d1,
                             uint2* __restrict__ out)
{
    long tot = (long)Jtot * N;
    for (long idx = (long)blockIdx.x * blockDim.x + threadIdx.x; idx < tot;
         idx += (long)gridDim.x * blockDim.x) {
        int j = (int)(idx / N), n = (int)(idx % N);
        float v[2];
        #pragma unroll
        for (int e = 0; e < 2; e++) {
            int k = 2 * j + e, row = -1;
            if (k >= d1 && k < d1 + l1) row = s1 + (k - d1);
            else if (k >= d0 && k < d0 + l0) row = s0 + (k - d0);
            v[e] = (row < 0) ? 0.f : W[(size_t)row * N + n];
        }
        out[idx] = splitpack(v[0], v[1]);
    }
}

// ---------------- f_atoms -> packed ----------------
__global__ void pack_fa_kernel(const float* __restrict__ fa, uint2* __restrict__ out)
{
    long tot = (long)NA * JP_FA;
    for (long idx = (long)blockIdx.x * blockDim.x + threadIdx.x; idx < tot;
         idx += (long)gridDim.x * blockDim.x) {
        int n = (int)(idx / JP_FA), j = (int)(idx % JP_FA);
        int k0 = 2 * j;
        float v0 = (k0     < FD) ? fa[(size_t)n * FD + k0]     : 0.f;
        float v1 = (k0 + 1 < FD) ? fa[(size_t)n * FD + k0 + 1] : 0.f;
        out[idx] = splitpack(v0, v1);
    }
}

// ---------------- build X packed: rows (n*3+c), K layout [a(134)|self(134)] ----------------
__global__ void build_X_kernel(const float* __restrict__ f_atoms, const float* __restrict__ f_bonds,
                               const int* __restrict__ a2a, const int* __restrict__ a2b,
                               uint2* __restrict__ Xp)
{
    int n = blockIdx.x;
    __shared__ int   nb[KNB];
    __shared__ float bond[KNB][3];
    __shared__ float stg[6][134];
    if (threadIdx.x < KNB) {
        int k = threadIdx.x;
        nb[k] = a2a[n * KNB + k];
        int b = a2b[n * KNB + k];
        bond[k][0] = f_bonds[(size_t)b * 3 + 0];
        bond[k][1] = f_bonds[(size_t)b * 3 + 1];
        bond[k][2] = f_bonds[(size_t)b * 3 + 2];
    }
    if (threadIdx.x < 6) stg[threadIdx.x][133] = 0.f;
    __syncthreads();
    float ms0 = 0.f, ms1 = 0.f, ms2 = 0.f;
    #pragma unroll
    for (int k = 0; k < KNB; k++) {
        float mk = (nb[k] > 0) ? 1.f : 0.f;
        ms0 += mk * bond[k][0];
        ms1 += mk * bond[k][1];
        ms2 += mk * bond[k][2];
    }
    for (int f = threadIdx.x; f < FD; f += blockDim.x) {
        float selfv = f_atoms[(size_t)n * FD + f];
        float a0 = 0.f, a1 = 0.f, a2 = 0.f;
        #pragma unroll
        for (int k = 0; k < KNB; k++) {
            float fv = f_atoms[(size_t)nb[k] * FD + f];
            a0 += fv * bond[k][0];
            a1 += fv * bond[k][1];
            a2 += fv * bond[k][2];
        }
        stg[0][f] = a0; stg[1][f] = a1; stg[2][f] = a2;
        stg[3][f] = selfv * ms0; stg[4][f] = selfv * ms1; stg[5][f] = selfv * ms2;
    }
    __syncthreads();
    for (int t = threadIdx.x; t < 3 * JP_X; t += blockDim.x) {
        int c = t / JP_X, j = t % JP_X;
        float v[2];
        #pragma unroll
        for (int e = 0; e < 2; e++) {
            int k = 2 * j + e;
            if (k < 134)      v[e] = stg[c][k];
            else if (k < 268) v[e] = stg[3 + c][k - 134];
            else              v[e] = 0.f;
        }
        Xp[((size_t)n * 3 + c) * JP_X + j] = splitpack(v[0], v[1]);
    }
}

// ---------------- message-passing gather -> packed (float2 loads; invnorm fused) ----------------
__global__ void gather_kernel(const float* __restrict__ s, const float* __restrict__ v,
                              const int* __restrict__ a2a,
                              uint2* __restrict__ sagg_p, uint2* __restrict__ vagg_p)
{
    int n = blockIdx.x;
    __shared__ int nb[KNB];
    if (threadIdx.x < KNB) nb[threadIdx.x] = a2a[n * KNB + threadIdx.x];
    __syncthreads();
    int cnt = 0;
    #pragma unroll
    for (int k = 0; k < KNB; k++) cnt += (nb[k] > 0) ? 1 : 0;
    const float sc = 1.f / (float)max(cnt, 1);

    const float2* s2 = (const float2*)s;
    const float2* v2 = (const float2*)v;
    size_t b0 = (size_t)nb[0] * (HD/2), b1 = (size_t)nb[1] * (HD/2), b2 = (size_t)nb[2] * (HD/2);
    size_t b3 = (size_t)nb[3] * (HD/2), b4 = (size_t)nb[4] * (HD/2), b5 = (size_t)nb[5] * (HD/2);
    for (int j = threadIdx.x; j < JP_H; j += blockDim.x) {
        float a0 = 0.f, a1 = 0.f;
        if (j < 550) {
            float2 x0 = s2[b0+j], x1 = s2[b1+j], x2 = s2[b2+j];
            float2 x3 = s2[b3+j], x4 = s2[b4+j], x5 = s2[b5+j];
            a0 = x0.x + x1.x + x2.x + x3.x + x4.x + x5.x;
            a1 = x0.y + x1.y + x2.y + x3.y + x4.y + x5.y;
        }
        sagg_p[(size_t)n * JP_H + j] = splitpack(a0, a1);
    }
    size_t c0 = b0*3, c1 = b1*3, c2 = b2*3, c3 = b3*3, c4 = b4*3, c5 = b5*3;
    for (int t = threadIdx.x; t < 3 * JP_H; t += blockDim.x) {
        int c = t / JP_H, j = t % JP_H;
        float a0 = 0.f, a1 = 0.f;
        if (j < 550) {
            size_t e = (size_t)c * (HD/2) + j;
            float2 x0 = v2[c0+e], x1 = v2[c1+e], x2 = v2[c2+e];
            float2 x3 = v2[c3+e], x4 = v2[c4+e], x5 = v2[c5+e];
            a0 = (x0.x + x1.x + x2.x + x3.x + x4.x + x5.x) * sc;
            a1 = (x0.y + x1.y + x2.y + x3.y + x4.y + x5.y) * sc;
        }
        vagg_p[((size_t)n * 3 + c) * JP_H + j] = splitpack(a0, a1);
    }
}

// ---------------- output-stage concat builders (gather fused, float2) ----------------
__global__ void build_osin_kernel(const float* __restrict__ fa, const float* __restrict__ s,
                                  const int* __restrict__ a2a, uint2* __restrict__ osin_p)
{
    int n = blockIdx.x;
    __shared__ int nb[KNB];
    if (threadIdx.x < KNB) nb[threadIdx.x] = a2a[n * KNB + threadIdx.x];
    __syncthreads();
    const float2* s2 = (const float2*)s;
    size_t b0 = (size_t)nb[0] * (HD/2), b1 = (size_t)nb[1] * (HD/2), b2 = (size_t)nb[2] * (HD/2);
    size_t b3 = (size_t)nb[3] * (HD/2), b4 = (size_t)nb[4] * (HD/2), b5 = (size_t)nb[5] * (HD/2);
    for (int j = threadIdx.x; j < JP_OS; j += blockDim.x) {
        float v0, v1;
        if (j < 67) {                       // k = 2j, 2j+1 both < 134 region (fa + pad)
            int k0 = 2 * j;
            v0 = (k0     < FD) ? fa[(size_t)n * FD + k0]     : 0.f;
            v1 = (k0 + 1 < FD) ? fa[(size_t)n * FD + k0 + 1] : 0.f;
        } else if (j < 617) {               // k in [134,1234): gather region, h = 2j-134
            size_t e = (size_t)j - 67;      // float2 index: (2j-134)/2
            float2 x0 = s2[b0+e], x1 = s2[b1+e], x2 = s2[b2+e];
            float2 x3 = s2[b3+e], x4 = s2[b4+e], x5 = s2[b5+e];
            v0 = x0.x + x1.x + x2.x + x3.x + x4.x + x5.x;
            v1 = x0.y + x1.y + x2.y + x3.y + x4.y + x5.y;
        } else { v0 = 0.f; v1 = 0.f; }
        osin_p[(size_t)n * JP_OS + j] = splitpack(v0, v1);
    }
}

__global__ void build_ovin_kernel(const float* __restrict__ vi, const float* __restrict__ v,
                                  const int* __restrict__ a2a, uint2* __restrict__ ovin_p)
{
    int n = blockIdx.x;
    __shared__ int nb[KNB];
    if (threadIdx.x < KNB) nb[threadIdx.x] = a2a[n * KNB + threadIdx.x];
    __syncthreads();
    const float2* vi2 = (const float2*)vi;
    const float2* v2  = (const float2*)v;
    size_t c0 = (size_t)nb[0]*3*(HD/2), c1 = (size_t)nb[1]*3*(HD/2), c2 = (size_t)nb[2]*3*(HD/2);
    size_t c3 = (size_t)nb[3]*3*(HD/2), c4 = (size_t)nb[4]*3*(HD/2), c5 = (size_t)nb[5]*3*(HD/2);
    for (int t = threadIdx.x; t < 3 * JP_OV; t += blockDim.x) {
        int c = t / JP_OV, j = t % JP_OV;
        float v0, v1;
        if (j < 550) {                      // vi part, k = 2j
            float2 x = vi2[((size_t)n * 3 + c) * (HD/2) + j];
            v0 = x.x; v1 = x.y;
        } else if (j < 1100) {              // gather part, h = c*HD + (2j-1100)
            size_t e = (size_t)c * (HD/2) + (j - 550);
            float2 x0 = v2[c0+e], x1 = v2[c1+e], x2 = v2[c2+e];
            float2 x3 = v2[c3+e], x4 = v2[c4+e], x5 = v2[c5+e];
            v0 = x0.x + x1.x + x2.x + x3.x + x4.x + x5.x;
            v1 = x0.y + x1.y + x2.y + x3.y + x4.y + x5.y;
        } else { v0 = 0.f; v1 = 0.f; }
        ovin_p[((size_t)n * 3 + c) * JP_OV + j] = splitpack(v0, v1);
    }
}

// o[n] = [osb | sum_c ovb]
__global__ void build_o_kernel(const float* __restrict__ osb, const float* __restrict__ ovb,
                               float* __restrict__ o)
{
    const float2* osb2 = (const float2*)osb;
    const float2* ovb2 = (const float2*)ovb;
    float2* o2 = (float2*)o;
    long tot = (long)NA * (FFK / 2);
    for (long idx = (long)blockIdx.x * blockDim.x + threadIdx.x; idx < tot;
         idx += (long)gridDim.x * blockDim.x) {
        int n = (int)(idx / (FFK / 2));
        int j = (int)(idx % (FFK / 2));
        float2 r;
        if (j < FHD / 2) {
            r = osb2[(size_t)n * (FHD/2) + j];
        } else {
            size_t b = (size_t)n * 3 * (FHD/2) + (j - FHD/2);
            float2 x0 = ovb2[b], x1 = ovb2[b + FHD/2], x2 = ovb2[b + 2*(FHD/2)];
            r.x = x0.x + x1.x + x2.x;
            r.y = x0.y + x1.y + x2.y;
        }
        o2[idx] = r;
    }
}

// ---------------- readout ----------------
__global__ void mol_start_kernel(const int* __restrict__ ids, int* __restrict__ start)
{
    int m = blockIdx.x * blockDim.x + threadIdx.x;
    if (m > NM) return;
    int lo = 0, hi = NA;
    while (lo < hi) {
        int mid = (lo + hi) >> 1;
        if (ids[mid] < m) lo = mid + 1; else hi = mid;
    }
    start[m] = lo;
}

__global__ void segment_mean_kernel(const float* __restrict__ o, const int* __restrict__ start,
                                    uint2* __restrict__ mol_p)
{
    int m = blockIdx.x;
    int s0 = start[m], e0 = start[m + 1];
    int cnt = e0 - s0;
    if (s0 == 0 && e0 > 0) cnt -= 1;   // atom 0 is padding
    float sc = 1.f / (float)max(cnt, 1);
    const float2* o2 = (const float2*)o;
    for (int t = threadIdx.x; t < JP_FF; t += blockDim.x) {
        float a0 = 0.f, a1 = 0.f;
        if (t < FFK / 2) {
            for (int n = s0; n < e0; n++) {
                if (n == 0) continue;
                float2 x = o2[(size_t)n * (FFK/2) + t];
                a0 += x.x; a1 += x.y;
            }
            a0 *= sc; a1 *= sc;
        }
        mol_p[(size_t)m * JP_FF + t] = splitpack(a0, a1);
    }
}

__global__ void ffn_out_kernel(const float* __restrict__ h, const float* __restrict__ W2,
                               const float* __restrict__ b2, float* __restrict__ out)
{
    int m = blockIdx.x;
    float acc = 0.f;
    for (int j = threadIdx.x; j < FHD; j += 256) acc += h[m * FHD + j] * W2[j];
    __shared__ float red[256];
    red[threadIdx.x] = acc;
    __syncthreads();
    for (int st = 128; st > 0; st >>= 1) {
        if (threadIdx.x < st) red[threadIdx.x] += red[threadIdx.x + st];
        __syncthreads();
    }
    if (threadIdx.x == 0) out[m] = red[0] + b2[0];
}

// ---------------- launch ----------------
extern "C" void kernel_launch(void* const* d_in, const int* in_sizes, int n_in,
                              void* d_out, int out_size)
{
    const float* f_atoms = (const float*)d_in[0];
    const float* f_bonds = (const float*)d_in[1];
    const float* W_is    = (const float*)d_in[2];
    const float* W_iv    = (const float*)d_in[3];
    const float* W_hs    = (const float*)d_in[4];
    const float* W_hv    = (const float*)d_in[5];
    const float* W_os    = (const float*)d_in[6];
    const float* b_os    = (const float*)d_in[7];
    const float* W_ov    = (const float*)d_in[8];
    const float* b_ov    = (const float*)d_in[9];
    const float* ffn_W1  = (const float*)d_in[10];
    const float* ffn_b1  = (const float*)d_in[11];
    const float* ffn_W2  = (const float*)d_in[12];
    const float* ffn_b2  = (const float*)d_in[13];
    const int*   a2a     = (const int*)d_in[14];
    const int*   a2b     = (const int*)d_in[15];
    const int*   mol_ids = (const int*)d_in[16];
    float*       out     = (float*)d_out;

    uint2 *p_fa, *p_X, *p_sagg, *p_vagg, *p_osin, *p_ovin, *p_mol;
    uint2 *p_Wis, *p_Wiv, *p_Whs, *p_Whv, *p_Wos, *p_Wov, *p_Wff;
    float *p_si, *p_s, *p_vi, *p_v, *p_osb, *p_ovb, *p_o, *p_h;
    int* p_molstart;
    cudaGetSymbolAddress((void**)&p_fa,   g_fa_p);
    cudaGetSymbolAddress((void**)&p_X,    g_X_p);
    cudaGetSymbolAddress((void**)&p_sagg, g_sagg_p);
    cudaGetSymbolAddress((void**)&p_vagg, g_vagg_p);
    cudaGetSymbolAddress((void**)&p_osin, g_osin_p);
    cudaGetSymbolAddress((void**)&p_ovin, g_ovin_p);
    cudaGetSymbolAddress((void**)&p_mol,  g_mol_p);
    cudaGetSymbolAddress((void**)&p_Wis,  g_Wis_p);
    cudaGetSymbolAddress((void**)&p_Wiv,  g_Wiv_p);
    cudaGetSymbolAddress((void**)&p_Whs,  g_Whs_p);
    cudaGetSymbolAddress((void**)&p_Whv,  g_Whv_p);
    cudaGetSymbolAddress((void**)&p_Wos,  g_Wos_p);
    cudaGetSymbolAddress((void**)&p_Wov,  g_Wov_p);
    cudaGetSymbolAddress((void**)&p_Wff,  g_Wff_p);
    cudaGetSymbolAddress((void**)&p_si,   g_si);
    cudaGetSymbolAddress((void**)&p_s,    g_s);
    cudaGetSymbolAddress((void**)&p_vi,   g_vi);
    cudaGetSymbolAddress((void**)&p_v,    g_v);
    cudaGetSymbolAddress((void**)&p_osb,  g_osb);
    cudaGetSymbolAddress((void**)&p_ovb,  g_ovb);
    cudaGetSymbolAddress((void**)&p_o,    g_o);
    cudaGetSymbolAddress((void**)&p_h,    g_h);
    cudaGetSymbolAddress((void**)&p_molstart, g_molstart);

    cudaFuncSetAttribute(bgemm_kernel<true,false,false,true>,
                         cudaFuncAttributeMaxDynamicSharedMemorySize, SMEM_GEMM);
    cudaFuncSetAttribute(bgemm_kernel<true,true,false,false>,
                         cudaFuncAttributeMaxDynamicSharedMemorySize, SMEM_GEMM);
    cudaFuncSetAttribute(bgemm_kernel<true,false,true,false>,
                         cudaFuncAttributeMaxDynamicSharedMemorySize, SMEM_GEMM);

    // 0. weight packing
    packW_kernel<<<512, 256>>>(W_is, HD, JP_FA, 0, 133, 0, 0, 0, 0, p_Wis);
    packW_kernel<<<512, 256>>>(W_iv, HD, JP_X, 0, 133, 0, 133, 133, 134, p_Wiv);
    packW_kernel<<<1024, 256>>>(W_hs, HD, JP_H, 0, 1100, 0, 0, 0, 0, p_Whs);
    packW_kernel<<<1024, 256>>>(W_hv, HD, JP_H, 0, 1100, 0, 0, 0, 0, p_Whv);
    packW_kernel<<<1024, 256>>>(W_os, FHD, JP_OS, 0, 133, 0, 133, 1100, 134, p_Wos);
    packW_kernel<<<1024, 256>>>(W_ov, FHD, JP_OV, 0, 2200, 0, 0, 0, 0, p_Wov);
    packW_kernel<<<1024, 256>>>(ffn_W1, FHD, JP_FF, 0, 1400, 0, 0, 0, 0, p_Wff);

    // 1. prep
    pack_fa_kernel<<<2048, 256>>>(f_atoms, p_fa);
    build_X_kernel<<<NA, 192>>>(f_atoms, f_bonds, a2a, a2b, p_X);

    // 2. si = f_atoms @ W_is
    dim3 gsi((HD + 127) / 128, (NA + 127) / 128);
    bgemm_kernel<true, false, false, true><<<gsi, 256, SMEM_GEMM>>>(
        p_fa, p_Wis, nullptr, nullptr, p_s, p_si, NA, HD, 5, JP_FA);

    // 3. vi = X @ W_iv
    dim3 gvi((HD + 127) / 128, (3 * NA + 127) / 128);
    bgemm_kernel<true, false, false, true><<<gvi, 256, SMEM_GEMM>>>(
        p_X, p_Wiv, nullptr, nullptr, p_v, p_vi, 3 * NA, HD, 9, JP_X);

    // 4. message passing
    for (int it = 0; it < 6; it++) {
        gather_kernel<<<NA, 256>>>(p_s, p_v, a2a, p_sagg, p_vagg);
        bgemm_kernel<true, true, false, false><<<gsi, 256, SMEM_GEMM>>>(
            p_sagg, p_Whs, p_si, nullptr, p_s, nullptr, NA, HD, 35, JP_H);
        bgemm_kernel<true, true, false, false><<<gvi, 256, SMEM_GEMM>>>(
            p_vagg, p_Whv, p_vi, nullptr, p_v, nullptr, 3 * NA, HD, 35, JP_H);
    }

    // 5. output stage (gathers fused into concat builders)
    build_osin_kernel<<<NA, 256>>>(f_atoms, p_s, a2a, p_osin);
    build_ovin_kernel<<<NA, 256>>>(p_vi, p_v, a2a, p_ovin);
    dim3 gos((FHD + 127) / 128, (NA + 127) / 128);
    bgemm_kernel<true, false, true, false><<<gos, 256, SMEM_GEMM>>>(
        p_osin, p_Wos, nullptr, b_os, p_osb, nullptr, NA, FHD, 39, JP_OS);
    dim3 gov((FHD + 127) / 128, (3 * NA + 127) / 128);
    bgemm_kernel<true, false, true, false><<<gov, 256, SMEM_GEMM>>>(
        p_ovin, p_Wov, nullptr, b_ov, p_ovb, nullptr, 3 * NA, FHD, 69, JP_OV);
    {
        long tot3 = (long)NA * (FFK / 2);
        build_o_kernel<<<(unsigned)((tot3 + 255) / 256), 256>>>(p_osb, p_ovb, p_o);
    }

    // 6. readout + FFN
    mol_start_kernel<<<4, 256>>>(mol_ids, p_molstart);
    segment_mean_kernel<<<NM, 256>>>(p_o, p_molstart, p_mol);
    dim3 gff((FHD + 127) / 128, (NM + 127) / 128);
    bgemm_kernel<true, false, true, false><<<gff, 256, SMEM_GEMM>>>(
        p_mol, p_Wff, nullptr, ffn_b1, p_h, nullptr, NM, FHD, 44, JP_FF);
    ffn_out_kernel<<<NM, 256>>>(p_h, ffn_W2, ffn_b2, out);
}

// round 10
// speedup vs baseline: 1.0874x; 1.0874x over previous
#include <cuda_runtime.h>
#include <cstdint>

// ---------------- Problem constants ----------------
#define NA   20001
#define FD   133
#define KNB  6
#define HD   1100
#define FHD  700
#define NM   800
#define FFK  1400

// K paddings in PAIRS (bf16x2). Multiples of 16 pairs = 32 elems (one stage).
#define JP_FA   80      // si : T=5
#define JP_X    144     // vi : T=9
#define JP_H    560     // hs/hv : T=35
#define JP_OS   624     // os : T=39
#define JP_OV   1104    // ov : T=69
#define JP_FF   704     // ffn : T=44

// ---------------- Scratch (device globals) ----------------
__device__ __align__(16) uint2 g_fa_p  [(size_t)NA * JP_FA];
__device__ __align__(16) uint2 g_X_p   [(size_t)NA * 3 * JP_X];
__device__ __align__(16) uint2 g_sagg_p[(size_t)NA * JP_H];
__device__ __align__(16) uint2 g_vagg_p[(size_t)NA * 3 * JP_H];
__device__ __align__(16) uint2 g_osin_p[(size_t)NA * JP_OS];
__device__ __align__(16) uint2 g_ovin_p[(size_t)NA * 3 * JP_OV];
__device__ __align__(16) uint2 g_mol_p [(size_t)NM * JP_FF];

__device__ __align__(16) uint2 g_Wis_p [(size_t)JP_FA * HD];
__device__ __align__(16) uint2 g_Wiv_p [(size_t)JP_X  * HD];
__device__ __align__(16) uint2 g_Whs_p [(size_t)JP_H  * HD];
__device__ __align__(16) uint2 g_Whv_p [(size_t)JP_H  * HD];
__device__ __align__(16) uint2 g_Wos_p [(size_t)JP_OS * FHD];
__device__ __align__(16) uint2 g_Wov_p [(size_t)JP_OV * FHD];
__device__ __align__(16) uint2 g_Wff_p [(size_t)JP_FF * FHD];

__device__ __align__(16) float g_si [(size_t)NA * HD];
__device__ __align__(16) float g_s  [(size_t)NA * HD];
__device__ __align__(16) float g_vi [(size_t)NA * 3 * HD];
__device__ __align__(16) float g_v  [(size_t)NA * 3 * HD];
__device__ __align__(16) float g_osb[(size_t)NA * FHD];
__device__ __align__(16) float g_ovb[(size_t)NA * 3 * FHD];
__device__ __align__(16) float g_o  [(size_t)NA * FFK];
__device__ __align__(16) float g_h  [NM * FHD];
__device__ int g_molstart[NM + 1];

// ---------------- bf16 split-pack helper ----------------
__device__ __forceinline__ uint2 splitpack(float x0, float x1) {
    unsigned h;
    asm("cvt.rn.bf16x2.f32 %0, %1, %2;" : "=r"(h) : "f"(x1), "f"(x0));
    float h0 = __uint_as_float(h << 16);
    float h1 = __uint_as_float(h & 0xFFFF0000u);
    unsigned l;
    asm("cvt.rn.bf16x2.f32 %0, %1, %2;" : "=r"(l) : "f"(x1 - h1), "f"(x0 - h0));
    return make_uint2(h, l);
}

__device__ __forceinline__ void cp16(void* dst_smem, const void* src, int bytes) {
    unsigned sa = (unsigned)__cvta_generic_to_shared(dst_smem);
    asm volatile("cp.async.ca.shared.global [%0], [%1], 16, %2;\n"
                 :: "r"(sa), "l"(src), "r"(bytes));
}

#define MMA_BF16(ACC, AF, BF)                                                   \
    asm volatile(                                                               \
        "mma.sync.aligned.m16n8k16.row.col.f32.bf16.bf16.f32 "                  \
        "{%0,%1,%2,%3}, {%4,%5,%6,%7}, {%8,%9}, {%0,%1,%2,%3};\n"               \
        : "+f"(ACC[0]), "+f"(ACC[1]), "+f"(ACC[2]), "+f"(ACC[3])                \
        : "r"(AF[0]), "r"(AF[1]), "r"(AF[2]), "r"(AF[3]),                       \
          "r"(BF[0]), "r"(BF[1]))

// ---------------- bf16x3 GEMM, BK=32 elems/stage, double-buffered (R8 structure) ----------------
#define ASTP 18
#define BSTP 132
#define STG_A (128 * ASTP)            // uint2
#define STG_B (16 * BSTP)             // uint2
#define STG_U2 (STG_A + STG_B)        // 4416 uint2 = 35328 B
#define SMEM_GEMM (2 * STG_U2 * 8)    // 70656 B

template<bool RELU, bool HAS_ADD, bool HAS_BIAS, bool WRITE_RAW>
__global__ __launch_bounds__(256, 2)
void bgemm_kernel(const uint2* __restrict__ A, const uint2* __restrict__ B,
                  const float* __restrict__ Add, const float* __restrict__ bias,
                  float* __restrict__ C, float* __restrict__ Craw,
                  int M, int N, int T, int ldp)
{
    extern __shared__ __align__(16) uint2 smem_u2[];

    const int tid = threadIdx.x;
    const int rowBase = blockIdx.y * 128;
    const int colBase = blockIdx.x * 128;
    const int warpId = tid >> 5;
    const int lane = tid & 31;
    const int g  = lane >> 2;
    const int tg = lane & 3;
    const int wm = (warpId & 1) * 64;
    const int wn = (warpId >> 1) * 32;

    float acc[4][4][4];
    #pragma unroll
    for (int mi = 0; mi < 4; mi++)
        #pragma unroll
        for (int ni = 0; ni < 4; ni++)
            #pragma unroll
            for (int j = 0; j < 4; j++) acc[mi][ni][j] = 0.f;

    auto load_stage = [&](int t, int st) {
        uint2* As = smem_u2 + st * STG_U2;
        uint2* Bs = As + STG_A;
        #pragma unroll
        for (int i = 0; i < 4; i++) {        // A: 1024 chunks (16B = 2 pairs)
            int c = tid + i * 256;
            int m = c >> 3, q = c & 7;
            int gm = rowBase + m;
            bool ok = gm < M;
            const uint2* src = ok ? (A + (size_t)gm * ldp + t * 16 + q * 2) : A;
            cp16(&As[m * ASTP + q * 2], src, ok ? 16 : 0);
        }
        #pragma unroll
        for (int i = 0; i < 4; i++) {        // B: 1024 chunks (2 cols)
            int c = tid + i * 256;
            int j = c >> 6, q = c & 63;
            int gn = colBase + q * 2;
            bool ok = gn < N;
            const uint2* src = ok ? (B + (size_t)(t * 16 + j) * N + gn) : B;
            cp16(&Bs[j * BSTP + q * 2], src, ok ? 16 : 0);
        }
        asm volatile("cp.async.commit_group;\n");
    };

    load_stage(0, 0);

    for (int t = 0; t < T; t++) {
        const int st = t & 1;
        if (t + 1 < T) {
            load_stage(t + 1, st ^ 1);
            asm volatile("cp.async.wait_group 1;\n");
        } else {
            asm volatile("cp.async.wait_group 0;\n");
        }
        __syncthreads();

        const uint2* As = smem_u2 + st * STG_U2;
        const uint2* Bs = As + STG_A;

        #pragma unroll
        for (int ks = 0; ks < 2; ks++) {
            const int kb = ks * 8;
            unsigned ah[4][4], al[4][4], bh[4][2], bl[4][2];
            #pragma unroll
            for (int mi = 0; mi < 4; mi++) {
                int r = wm + mi * 16 + g;
                uint2 p0 = As[r * ASTP + kb + tg];
                uint2 p1 = As[(r + 8) * ASTP + kb + tg];
                uint2 p2 = As[r * ASTP + kb + 4 + tg];
                uint2 p3 = As[(r + 8) * ASTP + kb + 4 + tg];
                ah[mi][0] = p0.x; ah[mi][1] = p1.x; ah[mi][2] = p2.x; ah[mi][3] = p3.x;
                al[mi][0] = p0.y; al[mi][1] = p1.y; al[mi][2] = p2.y; al[mi][3] = p3.y;
            }
            #pragma unroll
            for (int ni = 0; ni < 4; ni++) {
                int n = wn + ni * 8 + g;
                uint2 q0 = Bs[(kb + tg) * BSTP + n];
                uint2 q1 = Bs[(kb + 4 + tg) * BSTP + n];
                bh[ni][0] = q0.x; bh[ni][1] = q1.x;
                bl[ni][0] = q0.y; bl[ni][1] = q1.y;
            }
            #pragma unroll
            for (int mi = 0; mi < 4; mi++)
                #pragma unroll
                for (int ni = 0; ni < 4; ni++) {
                    MMA_BF16(acc[mi][ni], ah[mi], bl[ni]);   // hi*lo
                    MMA_BF16(acc[mi][ni], al[mi], bh[ni]);   // lo*hi
                    MMA_BF16(acc[mi][ni], ah[mi], bh[ni]);   // hi*hi last
                }
        }
        __syncthreads();
    }

    #pragma unroll
    for (int mi = 0; mi < 4; mi++) {
        int r0 = rowBase + wm + mi * 16 + g;
        #pragma unroll
        for (int ni = 0; ni < 4; ni++) {
            int cN = colBase + wn + ni * 8 + tg * 2;
            if (cN >= N) continue;
            #pragma unroll
            for (int half = 0; half < 2; half++) {
                int r = r0 + half * 8;
                if (r >= M) continue;
                size_t idx = (size_t)r * N + cN;
                float2 vv;
                vv.x = acc[mi][ni][half * 2 + 0];
                vv.y = acc[mi][ni][half * 2 + 1];
                if (HAS_ADD) {
                    float2 a = *(const float2*)(Add + idx);
                    vv.x += a.x; vv.y += a.y;
                }
                if (HAS_BIAS) {
                    float2 b = *(const float2*)(bias + cN);
                    vv.x += b.x; vv.y += b.y;
                }
                if (WRITE_RAW) *(float2*)(Craw + idx) = vv;
                if (RELU) { vv.x = fmaxf(vv.x, 0.f); vv.y = fmaxf(vv.y, 0.f); }
                *(float2*)(C + idx) = vv;
            }
        }
    }
}

// ---------------- weight split-pack (2-segment k remap), layout [j][n] ----------------
__global__ void packW_kernel(const float* __restrict__ W, int N, int Jtot,
                             int s0, int l0, int d0, int s1, int l1, int d1,
                             uint2* __restrict__ out)
{
    long tot = (long)Jtot * N;
    for (long idx = (long)blockIdx.x * blockDim.x + threadIdx.x; idx < tot;
         idx += (long)gridDim.x * blockDim.x) {
        int j = (int)(idx / N), n = (int)(idx % N);
        float v[2];
        #pragma unroll
        for (int e = 0; e < 2; e++) {
            int k = 2 * j + e, row = -1;
            if (k >= d1 && k < d1 + l1) row = s1 + (k - d1);
            else if (k >= d0 && k < d0 + l0) row = s0 + (k - d0);
            v[e] = (row < 0) ? 0.f : W[(size_t)row * N + n];
        }
        out[idx] = splitpack(v[0], v[1]);
    }
}

// ---------------- f_atoms -> packed ----------------
__global__ void pack_fa_kernel(const float* __restrict__ fa, uint2* __restrict__ out)
{
    long tot = (long)NA * JP_FA;
    for (long idx = (long)blockIdx.x * blockDim.x + threadIdx.x; idx < tot;
         idx += (long)gridDim.x * blockDim.x) {
        int n = (int)(idx / JP_FA), j = (int)(idx % JP_FA);
        int k0 = 2 * j;
        float v0 = (k0     < FD) ? fa[(size_t)n * FD + k0]     : 0.f;
        float v1 = (k0 + 1 < FD) ? fa[(size_t)n * FD + k0 + 1] : 0.f;
        out[idx] = splitpack(v0, v1);
    }
}

// ---------------- build X packed: rows (n*3+c), K layout [a(134)|self(134)] ----------------
__global__ void build_X_kernel(const float* __restrict__ f_atoms, const float* __restrict__ f_bonds,
                               const int* __restrict__ a2a, const int* __restrict__ a2b,
                               uint2* __restrict__ Xp)
{
    int n = blockIdx.x;
    __shared__ int   nb[KNB];
    __shared__ float bond[KNB][3];
    __shared__ float stg[6][134];
    if (threadIdx.x < KNB) {
        int k = threadIdx.x;
        nb[k] = a2a[n * KNB + k];
        int b = a2b[n * KNB + k];
        bond[k][0] = f_bonds[(size_t)b * 3 + 0];
        bond[k][1] = f_bonds[(size_t)b * 3 + 1];
        bond[k][2] = f_bonds[(size_t)b * 3 + 2];
    }
    if (threadIdx.x < 6) stg[threadIdx.x][133] = 0.f;
    __syncthreads();
    float ms0 = 0.f, ms1 = 0.f, ms2 = 0.f;
    #pragma unroll
    for (int k = 0; k < KNB; k++) {
        float mk = (nb[k] > 0) ? 1.f : 0.f;
        ms0 += mk * bond[k][0];
        ms1 += mk * bond[k][1];
        ms2 += mk * bond[k][2];
    }
    for (int f = threadIdx.x; f < FD; f += blockDim.x) {
        float selfv = f_atoms[(size_t)n * FD + f];
        float a0 = 0.f, a1 = 0.f, a2 = 0.f;
        #pragma unroll
        for (int k = 0; k < KNB; k++) {
            float fv = f_atoms[(size_t)nb[k] * FD + f];
            a0 += fv * bond[k][0];
            a1 += fv * bond[k][1];
            a2 += fv * bond[k][2];
        }
        stg[0][f] = a0; stg[1][f] = a1; stg[2][f] = a2;
        stg[3][f] = selfv * ms0; stg[4][f] = selfv * ms1; stg[5][f] = selfv * ms2;
    }
    __syncthreads();
    for (int t = threadIdx.x; t < 3 * JP_X; t += blockDim.x) {
        int c = t / JP_X, j = t % JP_X;
        float v[2];
        #pragma unroll
        for (int e = 0; e < 2; e++) {
            int k = 2 * j + e;
            if (k < 134)      v[e] = stg[c][k];
            else if (k < 268) v[e] = stg[3 + c][k - 134];
            else              v[e] = 0.f;
        }
        Xp[((size_t)n * 3 + c) * JP_X + j] = splitpack(v[0], v[1]);
    }
}

// ---------------- message-passing gather -> packed (float2 loads; invnorm fused) ----------------
__global__ void gather_kernel(const float* __restrict__ s, const float* __restrict__ v,
                              const int* __restrict__ a2a,
                              uint2* __restrict__ sagg_p, uint2* __restrict__ vagg_p)
{
    int n = blockIdx.x;
    __shared__ int nb[KNB];
    if (threadIdx.x < KNB) nb[threadIdx.x] = a2a[n * KNB + threadIdx.x];
    __syncthreads();
    int cnt = 0;
    #pragma unroll
    for (int k = 0; k < KNB; k++) cnt += (nb[k] > 0) ? 1 : 0;
    const float sc = 1.f / (float)max(cnt, 1);

    const float2* s2 = (const float2*)s;
    const float2* v2 = (const float2*)v;
    size_t b0 = (size_t)nb[0] * (HD/2), b1 = (size_t)nb[1] * (HD/2), b2 = (size_t)nb[2] * (HD/2);
    size_t b3 = (size_t)nb[3] * (HD/2), b4 = (size_t)nb[4] * (HD/2), b5 = (size_t)nb[5] * (HD/2);
    for (int j = threadIdx.x; j < JP_H; j += blockDim.x) {
        float a0 = 0.f, a1 = 0.f;
        if (j < 550) {
            float2 x0 = s2[b0+j], x1 = s2[b1+j], x2 = s2[b2+j];
            float2 x3 = s2[b3+j], x4 = s2[b4+j], x5 = s2[b5+j];
            a0 = x0.x + x1.x + x2.x + x3.x + x4.x + x5.x;
            a1 = x0.y + x1.y + x2.y + x3.y + x4.y + x5.y;
        }
        sagg_p[(size_t)n * JP_H + j] = splitpack(a0, a1);
    }
    size_t c0 = b0*3, c1 = b1*3, c2 = b2*3, c3 = b3*3, c4 = b4*3, c5 = b5*3;
    for (int t = threadIdx.x; t < 3 * JP_H; t += blockDim.x) {
        int c = t / JP_H, j = t % JP_H;
        float a0 = 0.f, a1 = 0.f;
        if (j < 550) {
            size_t e = (size_t)c * (HD/2) + j;
            float2 x0 = v2[c0+e], x1 = v2[c1+e], x2 = v2[c2+e];
            float2 x3 = v2[c3+e], x4 = v2[c4+e], x5 = v2[c5+e];
            a0 = (x0.x + x1.x + x2.x + x3.x + x4.x + x5.x) * sc;
            a1 = (x0.y + x1.y + x2.y + x3.y + x4.y + x5.y) * sc;
        }
        vagg_p[((size_t)n * 3 + c) * JP_H + j] = splitpack(a0, a1);
    }
}

// ---------------- output-stage concat builders (gather fused, float2) ----------------
__global__ void build_osin_kernel(const float* __restrict__ fa, const float* __restrict__ s,
                                  const int* __restrict__ a2a, uint2* __restrict__ osin_p)
{
    int n = blockIdx.x;
    __shared__ int nb[KNB];
    if (threadIdx.x < KNB) nb[threadIdx.x] = a2a[n * KNB + threadIdx.x];
    __syncthreads();
    const float2* s2 = (const float2*)s;
    size_t b0 = (size_t)nb[0] * (HD/2), b1 = (size_t)nb[1] * (HD/2), b2 = (size_t)nb[2] * (HD/2);
    size_t b3 = (size_t)nb[3] * (HD/2), b4 = (size_t)nb[4] * (HD/2), b5 = (size_t)nb[5] * (HD/2);
    for (int j = threadIdx.x; j < JP_OS; j += blockDim.x) {
        float v0, v1;
        if (j < 67) {
            int k0 = 2 * j;
            v0 = (k0     < FD) ? fa[(size_t)n * FD + k0]     : 0.f;
            v1 = (k0 + 1 < FD) ? fa[(size_t)n * FD + k0 + 1] : 0.f;
        } else if (j < 617) {
            size_t e = (size_t)j - 67;
            float2 x0 = s2[b0+e], x1 = s2[b1+e], x2 = s2[b2+e];
            float2 x3 = s2[b3+e], x4 = s2[b4+e], x5 = s2[b5+e];
            v0 = x0.x + x1.x + x2.x + x3.x + x4.x + x5.x;
            v1 = x0.y + x1.y + x2.y + x3.y + x4.y + x5.y;
        } else { v0 = 0.f; v1 = 0.f; }
        osin_p[(size_t)n * JP_OS + j] = splitpack(v0, v1);
    }
}

__global__ void build_ovin_kernel(const float* __restrict__ vi, const float* __restrict__ v,
                                  const int* __restrict__ a2a, uint2* __restrict__ ovin_p)
{
    int n = blockIdx.x;
    __shared__ int nb[KNB];
    if (threadIdx.x < KNB) nb[threadIdx.x] = a2a[n * KNB + threadIdx.x];
    __syncthreads();
    const float2* vi2 = (const float2*)vi;
    const float2* v2  = (const float2*)v;
    size_t c0 = (size_t)nb[0]*3*(HD/2), c1 = (size_t)nb[1]*3*(HD/2), c2 = (size_t)nb[2]*3*(HD/2);
    size_t c3 = (size_t)nb[3]*3*(HD/2), c4 = (size_t)nb[4]*3*(HD/2), c5 = (size_t)nb[5]*3*(HD/2);
    for (int t = threadIdx.x; t < 3 * JP_OV; t += blockDim.x) {
        int c = t / JP_OV, j = t % JP_OV;
        float v0, v1;
        if (j < 550) {
            float2 x = vi2[((size_t)n * 3 + c) * (HD/2) + j];
            v0 = x.x; v1 = x.y;
        } else if (j < 1100) {
            size_t e = (size_t)c * (HD/2) + (j - 550);
            float2 x0 = v2[c0+e], x1 = v2[c1+e], x2 = v2[c2+e];
            float2 x3 = v2[c3+e], x4 = v2[c4+e], x5 = v2[c5+e];
            v0 = x0.x + x1.x + x2.x + x3.x + x4.x + x5.x;
            v1 = x0.y + x1.y + x2.y + x3.y + x4.y + x5.y;
        } else { v0 = 0.f; v1 = 0.f; }
        ovin_p[((size_t)n * 3 + c) * JP_OV + j] = splitpack(v0, v1);
    }
}

// o[n] = [osb | sum_c ovb]
__global__ void build_o_kernel(const float* __restrict__ osb, const float* __restrict__ ovb,
                               float* __restrict__ o)
{
    const float2* osb2 = (const float2*)osb;
    const float2* ovb2 = (const float2*)ovb;
    float2* o2 = (float2*)o;
    long tot = (long)NA * (FFK / 2);
    for (long idx = (long)blockIdx.x * blockDim.x + threadIdx.x; idx < tot;
         idx += (long)gridDim.x * blockDim.x) {
        int n = (int)(idx / (FFK / 2));
        int j = (int)(idx % (FFK / 2));
        float2 r;
        if (j < FHD / 2) {
            r = osb2[(size_t)n * (FHD/2) + j];
        } else {
            size_t b = (size_t)n * 3 * (FHD/2) + (j - FHD/2);
            float2 x0 = ovb2[b], x1 = ovb2[b + FHD/2], x2 = ovb2[b + 2*(FHD/2)];
            r.x = x0.x + x1.x + x2.x;
            r.y = x0.y + x1.y + x2.y;
        }
        o2[idx] = r;
    }
}

// ---------------- readout ----------------
__global__ void mol_start_kernel(const int* __restrict__ ids, int* __restrict__ start)
{
    int m = blockIdx.x * blockDim.x + threadIdx.x;
    if (m > NM) return;
    int lo = 0, hi = NA;
    while (lo < hi) {
        int mid = (lo + hi) >> 1;
        if (ids[mid] < m) lo = mid + 1; else hi = mid;
    }
    start[m] = lo;
}

__global__ void segment_mean_kernel(const float* __restrict__ o, const int* __restrict__ start,
                                    uint2* __restrict__ mol_p)
{
    int m = blockIdx.x;
    int s0 = start[m], e0 = start[m + 1];
    int cnt = e0 - s0;
    if (s0 == 0 && e0 > 0) cnt -= 1;   // atom 0 is padding
    float sc = 1.f / (float)max(cnt, 1);
    const float2* o2 = (const float2*)o;
    for (int t = threadIdx.x; t < JP_FF; t += blockDim.x) {
        float a0 = 0.f, a1 = 0.f;
        if (t < FFK / 2) {
            for (int n = s0; n < e0; n++) {
                if (n == 0) continue;
                float2 x = o2[(size_t)n * (FFK/2) + t];
                a0 += x.x; a1 += x.y;
            }
            a0 *= sc; a1 *= sc;
        }
        mol_p[(size_t)m * JP_FF + t] = splitpack(a0, a1);
    }
}

__global__ void ffn_out_kernel(const float* __restrict__ h, const float* __restrict__ W2,
                               const float* __restrict__ b2, float* __restrict__ out)
{
    int m = blockIdx.x;
    float acc = 0.f;
    for (int j = threadIdx.x; j < FHD; j += 256) acc += h[m * FHD + j] * W2[j];
    __shared__ float red[256];
    red[threadIdx.x] = acc;
    __syncthreads();
    for (int st = 128; st > 0; st >>= 1) {
        if (threadIdx.x < st) red[threadIdx.x] += red[threadIdx.x + st];
        __syncthreads();
    }
    if (threadIdx.x == 0) out[m] = red[0] + b2[0];
}

// ---------------- launch ----------------
extern "C" void kernel_launch(void* const* d_in, const int* in_sizes, int n_in,
                              void* d_out, int out_size)
{
    const float* f_atoms = (const float*)d_in[0];
    const float* f_bonds = (const float*)d_in[1];
    const float* W_is    = (const float*)d_in[2];
    const float* W_iv    = (const float*)d_in[3];
    const float* W_hs    = (const float*)d_in[4];
    const float* W_hv    = (const float*)d_in[5];
    const float* W_os    = (const float*)d_in[6];
    const float* b_os    = (const float*)d_in[7];
    const float* W_ov    = (const float*)d_in[8];
    const float* b_ov    = (const float*)d_in[9];
    const float* ffn_W1  = (const float*)d_in[10];
    const float* ffn_b1  = (const float*)d_in[11];
    const float* ffn_W2  = (const float*)d_in[12];
    const float* ffn_b2  = (const float*)d_in[13];
    const int*   a2a     = (const int*)d_in[14];
    const int*   a2b     = (const int*)d_in[15];
    const int*   mol_ids = (const int*)d_in[16];
    float*       out     = (float*)d_out;

    uint2 *p_fa, *p_X, *p_sagg, *p_vagg, *p_osin, *p_ovin, *p_mol;
    uint2 *p_Wis, *p_Wiv, *p_Whs, *p_Whv, *p_Wos, *p_Wov, *p_Wff;
    float *p_si, *p_s, *p_vi, *p_v, *p_osb, *p_ovb, *p_o, *p_h;
    int* p_molstart;
    cudaGetSymbolAddress((void**)&p_fa,   g_fa_p);
    cudaGetSymbolAddress((void**)&p_X,    g_X_p);
    cudaGetSymbolAddress((void**)&p_sagg, g_sagg_p);
    cudaGetSymbolAddress((void**)&p_vagg, g_vagg_p);
    cudaGetSymbolAddress((void**)&p_osin, g_osin_p);
    cudaGetSymbolAddress((void**)&p_ovin, g_ovin_p);
    cudaGetSymbolAddress((void**)&p_mol,  g_mol_p);
    cudaGetSymbolAddress((void**)&p_Wis,  g_Wis_p);
    cudaGetSymbolAddress((void**)&p_Wiv,  g_Wiv_p);
    cudaGetSymbolAddress((void**)&p_Whs,  g_Whs_p);
    cudaGetSymbolAddress((void**)&p_Whv,  g_Whv_p);
    cudaGetSymbolAddress((void**)&p_Wos,  g_Wos_p);
    cudaGetSymbolAddress((void**)&p_Wov,  g_Wov_p);
    cudaGetSymbolAddress((void**)&p_Wff,  g_Wff_p);
    cudaGetSymbolAddress((void**)&p_si,   g_si);
    cudaGetSymbolAddress((void**)&p_s,    g_s);
    cudaGetSymbolAddress((void**)&p_vi,   g_vi);
    cudaGetSymbolAddress((void**)&p_v,    g_v);
    cudaGetSymbolAddress((void**)&p_osb,  g_osb);
    cudaGetSymbolAddress((void**)&p_ovb,  g_ovb);
    cudaGetSymbolAddress((void**)&p_o,    g_o);
    cudaGetSymbolAddress((void**)&p_h,    g_h);
    cudaGetSymbolAddress((void**)&p_molstart, g_molstart);

    cudaFuncSetAttribute(bgemm_kernel<true,false,false,true>,
                         cudaFuncAttributeMaxDynamicSharedMemorySize, SMEM_GEMM);
    cudaFuncSetAttribute(bgemm_kernel<true,true,false,false>,
                         cudaFuncAttributeMaxDynamicSharedMemorySize, SMEM_GEMM);
    cudaFuncSetAttribute(bgemm_kernel<true,false,true,false>,
                         cudaFuncAttributeMaxDynamicSharedMemorySize, SMEM_GEMM);

    // 0. weight packing
    packW_kernel<<<512, 256>>>(W_is, HD, JP_FA, 0, 133, 0, 0, 0, 0, p_Wis);
    packW_kernel<<<512, 256>>>(W_iv, HD, JP_X, 0, 133, 0, 133, 133, 134, p_Wiv);
    packW_kernel<<<1024, 256>>>(W_hs, HD, JP_H, 0, 1100, 0, 0, 0, 0, p_Whs);
    packW_kernel<<<1024, 256>>>(W_hv, HD, JP_H, 0, 1100, 0, 0, 0, 0, p_Whv);
    packW_kernel<<<1024, 256>>>(W_os, FHD, JP_OS, 0, 133, 0, 133, 1100, 134, p_Wos);
    packW_kernel<<<1024, 256>>>(W_ov, FHD, JP_OV, 0, 2200, 0, 0, 0, 0, p_Wov);
    packW_kernel<<<1024, 256>>>(ffn_W1, FHD, JP_FF, 0, 1400, 0, 0, 0, 0, p_Wff);

    // 1. prep
    pack_fa_kernel<<<2048, 256>>>(f_atoms, p_fa);
    build_X_kernel<<<NA, 192>>>(f_atoms, f_bonds, a2a, a2b, p_X);

    // 2. si = f_atoms @ W_is
    dim3 gsi((HD + 127) / 128, (NA + 127) / 128);
    bgemm_kernel<true, false, false, true><<<gsi, 256, SMEM_GEMM>>>(
        p_fa, p_Wis, nullptr, nullptr, p_s, p_si, NA, HD, 5, JP_FA);

    // 3. vi = X @ W_iv
    dim3 gvi((HD + 127) / 128, (3 * NA + 127) / 128);
    bgemm_kernel<true, false, false, true><<<gvi, 256, SMEM_GEMM>>>(
        p_X, p_Wiv, nullptr, nullptr, p_v, p_vi, 3 * NA, HD, 9, JP_X);

    // 4. message passing
    for (int it = 0; it < 6; it++) {
        gather_kernel<<<NA, 256>>>(p_s, p_v, a2a, p_sagg, p_vagg);
        bgemm_kernel<true, true, false, false><<<gsi, 256, SMEM_GEMM>>>(
            p_sagg, p_Whs, p_si, nullptr, p_s, nullptr, NA, HD, 35, JP_H);
        bgemm_kernel<true, true, false, false><<<gvi, 256, SMEM_GEMM>>>(
            p_vagg, p_Whv, p_vi, nullptr, p_v, nullptr, 3 * NA, HD, 35, JP_H);
    }

    // 5. output stage (gathers fused into concat builders)
    build_osin_kernel<<<NA, 256>>>(f_atoms, p_s, a2a, p_osin);
    build_ovin_kernel<<<NA, 256>>>(p_vi, p_v, a2a, p_ovin);
    dim3 gos((FHD + 127) / 128, (NA + 127) / 128);
    bgemm_kernel<true, false, true, false><<<gos, 256, SMEM_GEMM>>>(
        p_osin, p_Wos, nullptr, b_os, p_osb, nullptr, NA, FHD, 39, JP_OS);
    dim3 gov((FHD + 127) / 128, (3 * NA + 127) / 128);
    bgemm_kernel<true, false, true, false><<<gov, 256, SMEM_GEMM>>>(
        p_ovin, p_Wov, nullptr, b_ov, p_ovb, nullptr, 3 * NA, FHD, 69, JP_OV);
    {
        long tot3 = (long)NA * (FFK / 2);
        build_o_kernel<<<(unsigned)((tot3 + 255) / 256), 256>>>(p_osb, p_ovb, p_o);
    }

    // 6. readout + FFN
    mol_start_kernel<<<4, 256>>>(mol_ids, p_molstart);
    segment_mean_kernel<<<NM, 256>>>(p_o, p_molstart, p_mol);
    dim3 gff((FHD + 127) / 128, (NM + 127) / 128);
    bgemm_kernel<true, false, true, false><<<gff, 256, SMEM_GEMM>>>(
        p_mol, p_Wff, nullptr, ffn_b1, p_h, nullptr, NM, FHD, 44, JP_FF);
    ffn_out_kernel<<<NM, 256>>>(p_h, ffn_W2, ffn_b2, out);
}

// round 11
// speedup vs baseline: 1.1050x; 1.0162x over previous
#include <cuda_runtime.h>
#include <cstdint>

// ---------------- Problem constants ----------------
#define NA   20001
#define FD   133
#define KNB  6
#define HD   1100
#define FHD  700
#define NM   800
#define FFK  1400

// K paddings in PAIRS (bf16x2). Multiples of 16 pairs = 32 elems (one stage).
#define JP_FA   80      // si : T=5
#define JP_X    144     // vi : T=9
#define JP_H    560     // hs/hv : T=35
#define JP_OS   624     // os : T=39
#define JP_OV   1104    // ov : T=69
#define JP_FF   704     // ffn : T=44

// ---------------- Scratch (device globals) ----------------
__device__ __align__(16) uint2 g_fa_p  [(size_t)NA * JP_FA];
__device__ __align__(16) uint2 g_X_p   [(size_t)NA * 3 * JP_X];
__device__ __align__(16) uint2 g_sagg_p[(size_t)NA * JP_H];
__device__ __align__(16) uint2 g_vagg_p[(size_t)NA * 3 * JP_H];
__device__ __align__(16) uint2 g_osin_p[(size_t)NA * JP_OS];
__device__ __align__(16) uint2 g_ovin_p[(size_t)NA * 3 * JP_OV];
__device__ __align__(16) uint2 g_mol_p [(size_t)NM * JP_FF];

__device__ __align__(16) uint2 g_Wis_p [(size_t)JP_FA * HD];
__device__ __align__(16) uint2 g_Wiv_p [(size_t)JP_X  * HD];
__device__ __align__(16) uint2 g_Whs_p [(size_t)JP_H  * HD];
__device__ __align__(16) uint2 g_Whv_p [(size_t)JP_H  * HD];
__device__ __align__(16) uint2 g_Wos_p [(size_t)JP_OS * FHD];
__device__ __align__(16) uint2 g_Wov_p [(size_t)JP_OV * FHD];
__device__ __align__(16) uint2 g_Wff_p [(size_t)JP_FF * FHD];

__device__ __align__(16) float g_si [(size_t)NA * HD];
__device__ __align__(16) float g_s  [(size_t)NA * HD];
__device__ __align__(16) float g_vi [(size_t)NA * 3 * HD];
__device__ __align__(16) float g_v  [(size_t)NA * 3 * HD];
__device__ __align__(16) float g_osb[(size_t)NA * FHD];
__device__ __align__(16) float g_ovb[(size_t)NA * 3 * FHD];
__device__ __align__(16) float g_o  [(size_t)NA * FFK];
__device__ __align__(16) float g_h  [NM * FHD];
__device__ int g_molstart[NM + 1];

// ---------------- bf16 split-pack helper ----------------
__device__ __forceinline__ uint2 splitpack(float x0, float x1) {
    unsigned h;
    asm("cvt.rn.bf16x2.f32 %0, %1, %2;" : "=r"(h) : "f"(x1), "f"(x0));
    float h0 = __uint_as_float(h << 16);
    float h1 = __uint_as_float(h & 0xFFFF0000u);
    unsigned l;
    asm("cvt.rn.bf16x2.f32 %0, %1, %2;" : "=r"(l) : "f"(x1 - h1), "f"(x0 - h0));
    return make_uint2(h, l);
}

__device__ __forceinline__ void cp16(void* dst_smem, const void* src, int bytes) {
    unsigned sa = (unsigned)__cvta_generic_to_shared(dst_smem);
    asm volatile("cp.async.ca.shared.global [%0], [%1], 16, %2;\n"
                 :: "r"(sa), "l"(src), "r"(bytes));
}

#define MMA_BF16(ACC, AF, BF)                                                   \
    asm volatile(                                                               \
        "mma.sync.aligned.m16n8k16.row.col.f32.bf16.bf16.f32 "                  \
        "{%0,%1,%2,%3}, {%4,%5,%6,%7}, {%8,%9}, {%0,%1,%2,%3};\n"               \
        : "+f"(ACC[0]), "+f"(ACC[1]), "+f"(ACC[2]), "+f"(ACC[3])                \
        : "r"(AF[0]), "r"(AF[1]), "r"(AF[2]), "r"(AF[3]),                       \
          "r"(BF[0]), "r"(BF[1]))

// ---------------- bf16x3 GEMM, BK=32/stage, double-buffered, ONE sync/stage ----------------
// Hazard analysis: load for stage t+1 targets buffer (t+1)&1, which stage t-1
// computed from. The sync at stage t happens AFTER every warp finished stage
// t-1's MMAs (compute is the last thing in an iteration), so issuing the load
// after the sync is race-free. Only one cp.async group is ever pending at the
// wait, hence wait_group 0.
#define ASTP 18
#define BSTP 132
#define STG_A (128 * ASTP)            // uint2
#define STG_B (16 * BSTP)             // uint2
#define STG_U2 (STG_A + STG_B)        // 4416 uint2 = 35328 B
#define SMEM_GEMM (2 * STG_U2 * 8)    // 70656 B

template<bool RELU, bool HAS_ADD, bool HAS_BIAS, bool WRITE_RAW>
__global__ __launch_bounds__(256, 2)
void bgemm_kernel(const uint2* __restrict__ A, const uint2* __restrict__ B,
                  const float* __restrict__ Add, const float* __restrict__ bias,
                  float* __restrict__ C, float* __restrict__ Craw,
                  int M, int N, int T, int ldp)
{
    extern __shared__ __align__(16) uint2 smem_u2[];

    const int tid = threadIdx.x;
    const int rowBase = blockIdx.y * 128;
    const int colBase = blockIdx.x * 128;
    const int warpId = tid >> 5;
    const int lane = tid & 31;
    const int g  = lane >> 2;
    const int tg = lane & 3;
    const int wm = (warpId & 1) * 64;
    const int wn = (warpId >> 1) * 32;

    float acc[4][4][4];
    #pragma unroll
    for (int mi = 0; mi < 4; mi++)
        #pragma unroll
        for (int ni = 0; ni < 4; ni++)
            #pragma unroll
            for (int j = 0; j < 4; j++) acc[mi][ni][j] = 0.f;

    auto load_stage = [&](int t, int st) {
        uint2* As = smem_u2 + st * STG_U2;
        uint2* Bs = As + STG_A;
        #pragma unroll
        for (int i = 0; i < 4; i++) {        // A: 1024 chunks (16B = 2 pairs)
            int c = tid + i * 256;
            int m = c >> 3, q = c & 7;
            int gm = rowBase + m;
            bool ok = gm < M;
            const uint2* src = ok ? (A + (size_t)gm * ldp + t * 16 + q * 2) : A;
            cp16(&As[m * ASTP + q * 2], src, ok ? 16 : 0);
        }
        #pragma unroll
        for (int i = 0; i < 4; i++) {        // B: 1024 chunks (2 cols)
            int c = tid + i * 256;
            int j = c >> 6, q = c & 63;
            int gn = colBase + q * 2;
            bool ok = gn < N;
            const uint2* src = ok ? (B + (size_t)(t * 16 + j) * N + gn) : B;
            cp16(&Bs[j * BSTP + q * 2], src, ok ? 16 : 0);
        }
        asm volatile("cp.async.commit_group;\n");
    };

    load_stage(0, 0);

    for (int t = 0; t < T; t++) {
        const int st = t & 1;
        asm volatile("cp.async.wait_group 0;\n");   // stage-t load complete
        __syncthreads();                            // + all warps done with stage t-1

        if (t + 1 < T) load_stage(t + 1, st ^ 1);   // in flight under stage-t compute

        const uint2* As = smem_u2 + st * STG_U2;
        const uint2* Bs = As + STG_A;

        #pragma unroll
        for (int ks = 0; ks < 2; ks++) {
            const int kb = ks * 8;
            unsigned ah[4][4], al[4][4], bh[4][2], bl[4][2];
            #pragma unroll
            for (int mi = 0; mi < 4; mi++) {
                int r = wm + mi * 16 + g;
                uint2 p0 = As[r * ASTP + kb + tg];
                uint2 p1 = As[(r + 8) * ASTP + kb + tg];
                uint2 p2 = As[r * ASTP + kb + 4 + tg];
                uint2 p3 = As[(r + 8) * ASTP + kb + 4 + tg];
                ah[mi][0] = p0.x; ah[mi][1] = p1.x; ah[mi][2] = p2.x; ah[mi][3] = p3.x;
                al[mi][0] = p0.y; al[mi][1] = p1.y; al[mi][2] = p2.y; al[mi][3] = p3.y;
            }
            #pragma unroll
            for (int ni = 0; ni < 4; ni++) {
                int n = wn + ni * 8 + g;
                uint2 q0 = Bs[(kb + tg) * BSTP + n];
                uint2 q1 = Bs[(kb + 4 + tg) * BSTP + n];
                bh[ni][0] = q0.x; bh[ni][1] = q1.x;
                bl[ni][0] = q0.y; bl[ni][1] = q1.y;
            }
            #pragma unroll
            for (int mi = 0; mi < 4; mi++)
                #pragma unroll
                for (int ni = 0; ni < 4; ni++) {
                    MMA_BF16(acc[mi][ni], ah[mi], bl[ni]);   // hi*lo
                    MMA_BF16(acc[mi][ni], al[mi], bh[ni]);   // lo*hi
                    MMA_BF16(acc[mi][ni], ah[mi], bh[ni]);   // hi*hi last
                }
        }
    }

    #pragma unroll
    for (int mi = 0; mi < 4; mi++) {
        int r0 = rowBase + wm + mi * 16 + g;
        #pragma unroll
        for (int ni = 0; ni < 4; ni++) {
            int cN = colBase + wn + ni * 8 + tg * 2;
            if (cN >= N) continue;
            #pragma unroll
            for (int half = 0; half < 2; half++) {
                int r = r0 + half * 8;
                if (r >= M) continue;
                size_t idx = (size_t)r * N + cN;
                float2 vv;
                vv.x = acc[mi][ni][half * 2 + 0];
                vv.y = acc[mi][ni][half * 2 + 1];
                if (HAS_ADD) {
                    float2 a = *(const float2*)(Add + idx);
                    vv.x += a.x; vv.y += a.y;
                }
                if (HAS_BIAS) {
                    float2 b = *(const float2*)(bias + cN);
                    vv.x += b.x; vv.y += b.y;
                }
                if (WRITE_RAW) *(float2*)(Craw + idx) = vv;
                if (RELU) { vv.x = fmaxf(vv.x, 0.f); vv.y = fmaxf(vv.y, 0.f); }
                *(float2*)(C + idx) = vv;
            }
        }
    }
}

// ---------------- weight split-pack (2-segment k remap), layout [j][n] ----------------
__global__ void packW_kernel(const float* __restrict__ W, int N, int Jtot,
                             int s0, int l0, int d0, int s1, int l1, int d1,
                             uint2* __restrict__ out)
{
    long tot = (long)Jtot * N;
    for (long idx = (long)blockIdx.x * blockDim.x + threadIdx.x; idx < tot;
         idx += (long)gridDim.x * blockDim.x) {
        int j = (int)(idx / N), n = (int)(idx % N);
        float v[2];
        #pragma unroll
        for (int e = 0; e < 2; e++) {
            int k = 2 * j + e, row = -1;
            if (k >= d1 && k < d1 + l1) row = s1 + (k - d1);
            else if (k >= d0 && k < d0 + l0) row = s0 + (k - d0);
            v[e] = (row < 0) ? 0.f : W[(size_t)row * N + n];
        }
        out[idx] = splitpack(v[0], v[1]);
    }
}

// ---------------- f_atoms -> packed ----------------
__global__ void pack_fa_kernel(const float* __restrict__ fa, uint2* __restrict__ out)
{
    long tot = (long)NA * JP_FA;
    for (long idx = (long)blockIdx.x * blockDim.x + threadIdx.x; idx < tot;
         idx += (long)gridDim.x * blockDim.x) {
        int n = (int)(idx / JP_FA), j = (int)(idx % JP_FA);
        int k0 = 2 * j;
        float v0 = (k0     < FD) ? fa[(size_t)n * FD + k0]     : 0.f;
        float v1 = (k0 + 1 < FD) ? fa[(size_t)n * FD + k0 + 1] : 0.f;
        out[idx] = splitpack(v0, v1);
    }
}

// ---------------- build X packed: rows (n*3+c), K layout [a(134)|self(134)] ----------------
__global__ void build_X_kernel(const float* __restrict__ f_atoms, const float* __restrict__ f_bonds,
                               const int* __restrict__ a2a, const int* __restrict__ a2b,
                               uint2* __restrict__ Xp)
{
    int n = blockIdx.x;
    __shared__ int   nb[KNB];
    __shared__ float bond[KNB][3];
    __shared__ float stg[6][134];
    if (threadIdx.x < KNB) {
        int k = threadIdx.x;
        nb[k] = a2a[n * KNB + k];
        int b = a2b[n * KNB + k];
        bond[k][0] = f_bonds[(size_t)b * 3 + 0];
        bond[k][1] = f_bonds[(size_t)b * 3 + 1];
        bond[k][2] = f_bonds[(size_t)b * 3 + 2];
    }
    if (threadIdx.x < 6) stg[threadIdx.x][133] = 0.f;
    __syncthreads();
    float ms0 = 0.f, ms1 = 0.f, ms2 = 0.f;
    #pragma unroll
    for (int k = 0; k < KNB; k++) {
        float mk = (nb[k] > 0) ? 1.f : 0.f;
        ms0 += mk * bond[k][0];
        ms1 += mk * bond[k][1];
        ms2 += mk * bond[k][2];
    }
    for (int f = threadIdx.x; f < FD; f += blockDim.x) {
        float selfv = f_atoms[(size_t)n * FD + f];
        float a0 = 0.f, a1 = 0.f, a2 = 0.f;
        #pragma unroll
        for (int k = 0; k < KNB; k++) {
            float fv = f_atoms[(size_t)nb[k] * FD + f];
            a0 += fv * bond[k][0];
            a1 += fv * bond[k][1];
            a2 += fv * bond[k][2];
        }
        stg[0][f] = a0; stg[1][f] = a1; stg[2][f] = a2;
        stg[3][f] = selfv * ms0; stg[4][f] = selfv * ms1; stg[5][f] = selfv * ms2;
    }
    __syncthreads();
    for (int t = threadIdx.x; t < 3 * JP_X; t += blockDim.x) {
        int c = t / JP_X, j = t % JP_X;
        float v[2];
        #pragma unroll
        for (int e = 0; e < 2; e++) {
            int k = 2 * j + e;
            if (k < 134)      v[e] = stg[c][k];
            else if (k < 268) v[e] = stg[3 + c][k - 134];
            else              v[e] = 0.f;
        }
        Xp[((size_t)n * 3 + c) * JP_X + j] = splitpack(v[0], v[1]);
    }
}

// ---------------- message-passing gather -> packed (float2 loads; invnorm fused) ----------------
__global__ void gather_kernel(const float* __restrict__ s, const float* __restrict__ v,
                              const int* __restrict__ a2a,
                              uint2* __restrict__ sagg_p, uint2* __restrict__ vagg_p)
{
    int n = blockIdx.x;
    __shared__ int nb[KNB];
    if (threadIdx.x < KNB) nb[threadIdx.x] = a2a[n * KNB + threadIdx.x];
    __syncthreads();
    int cnt = 0;
    #pragma unroll
    for (int k = 0; k < KNB; k++) cnt += (nb[k] > 0) ? 1 : 0;
    const float sc = 1.f / (float)max(cnt, 1);

    const float2* s2 = (const float2*)s;
    const float2* v2 = (const float2*)v;
    size_t b0 = (size_t)nb[0] * (HD/2), b1 = (size_t)nb[1] * (HD/2), b2 = (size_t)nb[2] * (HD/2);
    size_t b3 = (size_t)nb[3] * (HD/2), b4 = (size_t)nb[4] * (HD/2), b5 = (size_t)nb[5] * (HD/2);
    for (int j = threadIdx.x; j < JP_H; j += blockDim.x) {
        float a0 = 0.f, a1 = 0.f;
        if (j < 550) {
            float2 x0 = s2[b0+j], x1 = s2[b1+j], x2 = s2[b2+j];
            float2 x3 = s2[b3+j], x4 = s2[b4+j], x5 = s2[b5+j];
            a0 = x0.x + x1.x + x2.x + x3.x + x4.x + x5.x;
            a1 = x0.y + x1.y + x2.y + x3.y + x4.y + x5.y;
        }
        sagg_p[(size_t)n * JP_H + j] = splitpack(a0, a1);
    }
    size_t c0 = b0*3, c1 = b1*3, c2 = b2*3, c3 = b3*3, c4 = b4*3, c5 = b5*3;
    for (int t = threadIdx.x; t < 3 * JP_H; t += blockDim.x) {
        int c = t / JP_H, j = t % JP_H;
        float a0 = 0.f, a1 = 0.f;
        if (j < 550) {
            size_t e = (size_t)c * (HD/2) + j;
            float2 x0 = v2[c0+e], x1 = v2[c1+e], x2 = v2[c2+e];
            float2 x3 = v2[c3+e], x4 = v2[c4+e], x5 = v2[c5+e];
            a0 = (x0.x + x1.x + x2.x + x3.x + x4.x + x5.x) * sc;
            a1 = (x0.y + x1.y + x2.y + x3.y + x4.y + x5.y) * sc;
        }
        vagg_p[((size_t)n * 3 + c) * JP_H + j] = splitpack(a0, a1);
    }
}

// ---------------- output-stage concat builders (gather fused, float2) ----------------
__global__ void build_osin_kernel(const float* __restrict__ fa, const float* __restrict__ s,
                                  const int* __restrict__ a2a, uint2* __restrict__ osin_p)
{
    int n = blockIdx.x;
    __shared__ int nb[KNB];
    if (threadIdx.x < KNB) nb[threadIdx.x] = a2a[n * KNB + threadIdx.x];
    __syncthreads();
    const float2* s2 = (const float2*)s;
    size_t b0 = (size_t)nb[0] * (HD/2), b1 = (size_t)nb[1] * (HD/2), b2 = (size_t)nb[2] * (HD/2);
    size_t b3 = (size_t)nb[3] * (HD/2), b4 = (size_t)nb[4] * (HD/2), b5 = (size_t)nb[5] * (HD/2);
    for (int j = threadIdx.x; j < JP_OS; j += blockDim.x) {
        float v0, v1;
        if (j < 67) {
            int k0 = 2 * j;
            v0 = (k0     < FD) ? fa[(size_t)n * FD + k0]     : 0.f;
            v1 = (k0 + 1 < FD) ? fa[(size_t)n * FD + k0 + 1] : 0.f;
        } else if (j < 617) {
            size_t e = (size_t)j - 67;
            float2 x0 = s2[b0+e], x1 = s2[b1+e], x2 = s2[b2+e];
            float2 x3 = s2[b3+e], x4 = s2[b4+e], x5 = s2[b5+e];
            v0 = x0.x + x1.x + x2.x + x3.x + x4.x + x5.x;
            v1 = x0.y + x1.y + x2.y + x3.y + x4.y + x5.y;
        } else { v0 = 0.f; v1 = 0.f; }
        osin_p[(size_t)n * JP_OS + j] = splitpack(v0, v1);
    }
}

__global__ void build_ovin_kernel(const float* __restrict__ vi, const float* __restrict__ v,
                                  const int* __restrict__ a2a, uint2* __restrict__ ovin_p)
{
    int n = blockIdx.x;
    __shared__ int nb[KNB];
    if (threadIdx.x < KNB) nb[threadIdx.x] = a2a[n * KNB + threadIdx.x];
    __syncthreads();
    const float2* vi2 = (const float2*)vi;
    const float2* v2  = (const float2*)v;
    size_t c0 = (size_t)nb[0]*3*(HD/2), c1 = (size_t)nb[1]*3*(HD/2), c2 = (size_t)nb[2]*3*(HD/2);
    size_t c3 = (size_t)nb[3]*3*(HD/2), c4 = (size_t)nb[4]*3*(HD/2), c5 = (size_t)nb[5]*3*(HD/2);
    for (int t = threadIdx.x; t < 3 * JP_OV; t += blockDim.x) {
        int c = t / JP_OV, j = t % JP_OV;
        float v0, v1;
        if (j < 550) {
            float2 x = vi2[((size_t)n * 3 + c) * (HD/2) + j];
            v0 = x.x; v1 = x.y;
        } else if (j < 1100) {
            size_t e = (size_t)c * (HD/2) + (j - 550);
            float2 x0 = v2[c0+e], x1 = v2[c1+e], x2 = v2[c2+e];
            float2 x3 = v2[c3+e], x4 = v2[c4+e], x5 = v2[c5+e];
            v0 = x0.x + x1.x + x2.x + x3.x + x4.x + x5.x;
            v1 = x0.y + x1.y + x2.y + x3.y + x4.y + x5.y;
        } else { v0 = 0.f; v1 = 0.f; }
        ovin_p[((size_t)n * 3 + c) * JP_OV + j] = splitpack(v0, v1);
    }
}

// o[n] = [osb | sum_c ovb]
__global__ void build_o_kernel(const float* __restrict__ osb, const float* __restrict__ ovb,
                               float* __restrict__ o)
{
    const float2* osb2 = (const float2*)osb;
    const float2* ovb2 = (const float2*)ovb;
    float2* o2 = (float2*)o;
    long tot = (long)NA * (FFK / 2);
    for (long idx = (long)blockIdx.x * blockDim.x + threadIdx.x; idx < tot;
         idx += (long)gridDim.x * blockDim.x) {
        int n = (int)(idx / (FFK / 2));
        int j = (int)(idx % (FFK / 2));
        float2 r;
        if (j < FHD / 2) {
            r = osb2[(size_t)n * (FHD/2) + j];
        } else {
            size_t b = (size_t)n * 3 * (FHD/2) + (j - FHD/2);
            float2 x0 = ovb2[b], x1 = ovb2[b + FHD/2], x2 = ovb2[b + 2*(FHD/2)];
            r.x = x0.x + x1.x + x2.x;
            r.y = x0.y + x1.y + x2.y;
        }
        o2[idx] = r;
    }
}

// ---------------- readout ----------------
__global__ void mol_start_kernel(const int* __restrict__ ids, int* __restrict__ start)
{
    int m = blockIdx.x * blockDim.x + threadIdx.x;
    if (m > NM) return;
    int lo = 0, hi = NA;
    while (lo < hi) {
        int mid = (lo + hi) >> 1;
        if (ids[mid] < m) lo = mid + 1; else hi = mid;
    }
    start[m] = lo;
}

__global__ void segment_mean_kernel(const float* __restrict__ o, const int* __restrict__ start,
                                    uint2* __restrict__ mol_p)
{
    int m = blockIdx.x;
    int s0 = start[m], e0 = start[m + 1];
    int cnt = e0 - s0;
    if (s0 == 0 && e0 > 0) cnt -= 1;   // atom 0 is padding
    float sc = 1.f / (float)max(cnt, 1);
    const float2* o2 = (const float2*)o;
    for (int t = threadIdx.x; t < JP_FF; t += blockDim.x) {
        float a0 = 0.f, a1 = 0.f;
        if (t < FFK / 2) {
            for (int n = s0; n < e0; n++) {
                if (n == 0) continue;
                float2 x = o2[(size_t)n * (FFK/2) + t];
                a0 += x.x; a1 += x.y;
            }
            a0 *= sc; a1 *= sc;
        }
        mol_p[(size_t)m * JP_FF + t] = splitpack(a0, a1);
    }
}

__global__ void ffn_out_kernel(const float* __restrict__ h, const float* __restrict__ W2,
                               const float* __restrict__ b2, float* __restrict__ out)
{
    int m = blockIdx.x;
    float acc = 0.f;
    for (int j = threadIdx.x; j < FHD; j += 256) acc += h[m * FHD + j] * W2[j];
    __shared__ float red[256];
    red[threadIdx.x] = acc;
    __syncthreads();
    for (int st = 128; st > 0; st >>= 1) {
        if (threadIdx.x < st) red[threadIdx.x] += red[threadIdx.x + st];
        __syncthreads();
    }
    if (threadIdx.x == 0) out[m] = red[0] + b2[0];
}

// ---------------- launch ----------------
extern "C" void kernel_launch(void* const* d_in, const int* in_sizes, int n_in,
                              void* d_out, int out_size)
{
    const float* f_atoms = (const float*)d_in[0];
    const float* f_bonds = (const float*)d_in[1];
    const float* W_is    = (const float*)d_in[2];
    const float* W_iv    = (const float*)d_in[3];
    const float* W_hs    = (const float*)d_in[4];
    const float* W_hv    = (const float*)d_in[5];
    const float* W_os    = (const float*)d_in[6];
    const float* b_os    = (const float*)d_in[7];
    const float* W_ov    = (const float*)d_in[8];
    const float* b_ov    = (const float*)d_in[9];
    const float* ffn_W1  = (const float*)d_in[10];
    const float* ffn_b1  = (const float*)d_in[11];
    const float* ffn_W2  = (const float*)d_in[12];
    const float* ffn_b2  = (const float*)d_in[13];
    const int*   a2a     = (const int*)d_in[14];
    const int*   a2b     = (const int*)d_in[15];
    const int*   mol_ids = (const int*)d_in[16];
    float*       out     = (float*)d_out;

    uint2 *p_fa, *p_X, *p_sagg, *p_vagg, *p_osin, *p_ovin, *p_mol;
    uint2 *p_Wis, *p_Wiv, *p_Whs, *p_Whv, *p_Wos, *p_Wov, *p_Wff;
    float *p_si, *p_s, *p_vi, *p_v, *p_osb, *p_ovb, *p_o, *p_h;
    int* p_molstart;
    cudaGetSymbolAddress((void**)&p_fa,   g_fa_p);
    cudaGetSymbolAddress((void**)&p_X,    g_X_p);
    cudaGetSymbolAddress((void**)&p_sagg, g_sagg_p);
    cudaGetSymbolAddress((void**)&p_vagg, g_vagg_p);
    cudaGetSymbolAddress((void**)&p_osin, g_osin_p);
    cudaGetSymbolAddress((void**)&p_ovin, g_ovin_p);
    cudaGetSymbolAddress((void**)&p_mol,  g_mol_p);
    cudaGetSymbolAddress((void**)&p_Wis,  g_Wis_p);
    cudaGetSymbolAddress((void**)&p_Wiv,  g_Wiv_p);
    cudaGetSymbolAddress((void**)&p_Whs,  g_Whs_p);
    cudaGetSymbolAddress((void**)&p_Whv,  g_Whv_p);
    cudaGetSymbolAddress((void**)&p_Wos,  g_Wos_p);
    cudaGetSymbolAddress((void**)&p_Wov,  g_Wov_p);
    cudaGetSymbolAddress((void**)&p_Wff,  g_Wff_p);
    cudaGetSymbolAddress((void**)&p_si,   g_si);
    cudaGetSymbolAddress((void**)&p_s,    g_s);
    cudaGetSymbolAddress((void**)&p_vi,   g_vi);
    cudaGetSymbolAddress((void**)&p_v,    g_v);
    cudaGetSymbolAddress((void**)&p_osb,  g_osb);
    cudaGetSymbolAddress((void**)&p_ovb,  g_ovb);
    cudaGetSymbolAddress((void**)&p_o,    g_o);
    cudaGetSymbolAddress((void**)&p_h,    g_h);
    cudaGetSymbolAddress((void**)&p_molstart, g_molstart);

    cudaFuncSetAttribute(bgemm_kernel<true,false,false,true>,
                         cudaFuncAttributeMaxDynamicSharedMemorySize, SMEM_GEMM);
    cudaFuncSetAttribute(bgemm_kernel<true,true,false,false>,
                         cudaFuncAttributeMaxDynamicSharedMemorySize, SMEM_GEMM);
    cudaFuncSetAttribute(bgemm_kernel<true,false,true,false>,
                         cudaFuncAttributeMaxDynamicSharedMemorySize, SMEM_GEMM);

    // 0. weight packing
    packW_kernel<<<512, 256>>>(W_is, HD, JP_FA, 0, 133, 0, 0, 0, 0, p_Wis);
    packW_kernel<<<512, 256>>>(W_iv, HD, JP_X, 0, 133, 0, 133, 133, 134, p_Wiv);
    packW_kernel<<<1024, 256>>>(W_hs, HD, JP_H, 0, 1100, 0, 0, 0, 0, p_Whs);
    packW_kernel<<<1024, 256>>>(W_hv, HD, JP_H, 0, 1100, 0, 0, 0, 0, p_Whv);
    packW_kernel<<<1024, 256>>>(W_os, FHD, JP_OS, 0, 133, 0, 133, 1100, 134, p_Wos);
    packW_kernel<<<1024, 256>>>(W_ov, FHD, JP_OV, 0, 2200, 0, 0, 0, 0, p_Wov);
    packW_kernel<<<1024, 256>>>(ffn_W1, FHD, JP_FF, 0, 1400, 0, 0, 0, 0, p_Wff);

    // 1. prep
    pack_fa_kernel<<<2048, 256>>>(f_atoms, p_fa);
    build_X_kernel<<<NA, 192>>>(f_atoms, f_bonds, a2a, a2b, p_X);

    // 2. si = f_atoms @ W_is
    dim3 gsi((HD + 127) / 128, (NA + 127) / 128);
    bgemm_kernel<true, false, false, true><<<gsi, 256, SMEM_GEMM>>>(
        p_fa, p_Wis, nullptr, nullptr, p_s, p_si, NA, HD, 5, JP_FA);

    // 3. vi = X @ W_iv
    dim3 gvi((HD + 127) / 128, (3 * NA + 127) / 128);
    bgemm_kernel<true, false, false, true><<<gvi, 256, SMEM_GEMM>>>(
        p_X, p_Wiv, nullptr, nullptr, p_v, p_vi, 3 * NA, HD, 9, JP_X);

    // 4. message passing
    for (int it = 0; it < 6; it++) {
        gather_kernel<<<NA, 256>>>(p_s, p_v, a2a, p_sagg, p_vagg);
        bgemm_kernel<true, true, false, false><<<gsi, 256, SMEM_GEMM>>>(
            p_sagg, p_Whs, p_si, nullptr, p_s, nullptr, NA, HD, 35, JP_H);
        bgemm_kernel<true, true, false, false><<<gvi, 256, SMEM_GEMM>>>(
            p_vagg, p_Whv, p_vi, nullptr, p_v, nullptr, 3 * NA, HD, 35, JP_H);
    }

    // 5. output stage (gathers fused into concat builders)
    build_osin_kernel<<<NA, 256>>>(f_atoms, p_s, a2a, p_osin);
    build_ovin_kernel<<<NA, 256>>>(p_vi, p_v, a2a, p_ovin);
    dim3 gos((FHD + 127) / 128, (NA + 127) / 128);
    bgemm_kernel<true, false, true, false><<<gos, 256, SMEM_GEMM>>>(
        p_osin, p_Wos, nullptr, b_os, p_osb, nullptr, NA, FHD, 39, JP_OS);
    dim3 gov((FHD + 127) / 128, (3 * NA + 127) / 128);
    bgemm_kernel<true, false, true, false><<<gov, 256, SMEM_GEMM>>>(
        p_ovin, p_Wov, nullptr, b_ov, p_ovb, nullptr, 3 * NA, FHD, 69, JP_OV);
    {
        long tot3 = (long)NA * (FFK / 2);
        build_o_kernel<<<(unsigned)((tot3 + 255) / 256), 256>>>(p_osb, p_ovb, p_o);
    }

    // 6. readout + FFN
    mol_start_kernel<<<4, 256>>>(mol_ids, p_molstart);
    segment_mean_kernel<<<NM, 256>>>(p_o, p_molstart, p_mol);
    dim3 gff((FHD + 127) / 128, (NM + 127) / 128);
    bgemm_kernel<true, false, true, false><<<gff, 256, SMEM_GEMM>>>(
        p_mol, p_Wff, nullptr, ffn_b1, p_h, nullptr, NM, FHD, 44, JP_FF);
    ffn_out_kernel<<<NM, 256>>>(p_h, ffn_W2, ffn_b2, out);
}

// round 12
// speedup vs baseline: 1.1199x; 1.0135x over previous
#include <cuda_runtime.h>
#include <cstdint>

// ---------------- Problem constants ----------------
#define NA   20001
#define FD   133
#define KNB  6
#define HD   1100
#define FHD  700
#define NM   800
#define FFK  1400

// K paddings in PAIRS (bf16x2). Multiples of 16 pairs = 32 elems (one stage).
#define JP_FA   80      // si : T=5
#define JP_X    144     // vi : T=9
#define JP_H    560     // hs/hv : T=35
#define JP_OS   624     // os : T=39
#define JP_OV   1104    // ov : T=69
#define JP_FF   704     // ffn : T=44

// ---------------- Scratch (device globals) ----------------
__device__ __align__(16) uint2 g_fa_p  [(size_t)NA * JP_FA];
__device__ __align__(16) uint2 g_X_p   [(size_t)NA * 3 * JP_X];
__device__ __align__(16) uint2 g_sagg_p[(size_t)NA * JP_H];
__device__ __align__(16) uint2 g_vagg_p[(size_t)NA * 3 * JP_H];
__device__ __align__(16) uint2 g_osin_p[(size_t)NA * JP_OS];
__device__ __align__(16) uint2 g_ovin_p[(size_t)NA * 3 * JP_OV];
__device__ __align__(16) uint2 g_mol_p [(size_t)NM * JP_FF];

__device__ __align__(16) uint2 g_Wis_p [(size_t)JP_FA * HD];
__device__ __align__(16) uint2 g_Wiv_p [(size_t)JP_X  * HD];
__device__ __align__(16) uint2 g_Whs_p [(size_t)JP_H  * HD];
__device__ __align__(16) uint2 g_Whv_p [(size_t)JP_H  * HD];
__device__ __align__(16) uint2 g_Wos_p [(size_t)JP_OS * FHD];
__device__ __align__(16) uint2 g_Wov_p [(size_t)JP_OV * FHD];
__device__ __align__(16) uint2 g_Wff_p [(size_t)JP_FF * FHD];

__device__ __align__(16) float g_si [(size_t)NA * HD];
__device__ __align__(16) float g_s  [(size_t)NA * HD];
__device__ __align__(16) float g_vi [(size_t)NA * 3 * HD];
__device__ __align__(16) float g_v  [(size_t)NA * 3 * HD];
__device__ __align__(16) float g_osb[(size_t)NA * FHD];
__device__ __align__(16) float g_ovb[(size_t)NA * 3 * FHD];
__device__ __align__(16) float g_o  [(size_t)NA * FFK];
__device__ __align__(16) float g_h  [NM * FHD];
__device__ int g_molstart[NM + 1];

// ---------------- bf16 split-pack helper ----------------
__device__ __forceinline__ uint2 splitpack(float x0, float x1) {
    unsigned h;
    asm("cvt.rn.bf16x2.f32 %0, %1, %2;" : "=r"(h) : "f"(x1), "f"(x0));
    float h0 = __uint_as_float(h << 16);
    float h1 = __uint_as_float(h & 0xFFFF0000u);
    unsigned l;
    asm("cvt.rn.bf16x2.f32 %0, %1, %2;" : "=r"(l) : "f"(x1 - h1), "f"(x0 - h0));
    return make_uint2(h, l);
}

__device__ __forceinline__ uint4 splitpack4(float4 a) {
    uint2 r0 = splitpack(a.x, a.y);
    uint2 r1 = splitpack(a.z, a.w);
    return make_uint4(r0.x, r0.y, r1.x, r1.y);
}

__device__ __forceinline__ void cp16(void* dst_smem, const void* src, int bytes) {
    unsigned sa = (unsigned)__cvta_generic_to_shared(dst_smem);
    asm volatile("cp.async.ca.shared.global [%0], [%1], 16, %2;\n"
                 :: "r"(sa), "l"(src), "r"(bytes));
}

#define MMA_BF16(ACC, AF, BF)                                                   \
    asm volatile(                                                               \
        "mma.sync.aligned.m16n8k16.row.col.f32.bf16.bf16.f32 "                  \
        "{%0,%1,%2,%3}, {%4,%5,%6,%7}, {%8,%9}, {%0,%1,%2,%3};\n"               \
        : "+f"(ACC[0]), "+f"(ACC[1]), "+f"(ACC[2]), "+f"(ACC[3])                \
        : "r"(AF[0]), "r"(AF[1]), "r"(AF[2]), "r"(AF[3]),                       \
          "r"(BF[0]), "r"(BF[1]))

// ---------------- bf16x3 GEMM, BK=32/stage, double-buffered, ONE sync/stage ----------------
#define ASTP 18
#define BSTP 132
#define STG_A (128 * ASTP)            // uint2
#define STG_B (16 * BSTP)             // uint2
#define STG_U2 (STG_A + STG_B)        // 4416 uint2 = 35328 B
#define SMEM_GEMM (2 * STG_U2 * 8)    // 70656 B

template<bool RELU, bool HAS_ADD, bool HAS_BIAS, bool WRITE_RAW>
__global__ __launch_bounds__(256, 2)
void bgemm_kernel(const uint2* __restrict__ A, const uint2* __restrict__ B,
                  const float* __restrict__ Add, const float* __restrict__ bias,
                  float* __restrict__ C, float* __restrict__ Craw,
                  int M, int N, int T, int ldp)
{
    extern __shared__ __align__(16) uint2 smem_u2[];

    const int tid = threadIdx.x;
    const int rowBase = blockIdx.y * 128;
    const int colBase = blockIdx.x * 128;
    const int warpId = tid >> 5;
    const int lane = tid & 31;
    const int g  = lane >> 2;
    const int tg = lane & 3;
    const int wm = (warpId & 1) * 64;
    const int wn = (warpId >> 1) * 32;

    float acc[4][4][4];
    #pragma unroll
    for (int mi = 0; mi < 4; mi++)
        #pragma unroll
        for (int ni = 0; ni < 4; ni++)
            #pragma unroll
            for (int j = 0; j < 4; j++) acc[mi][ni][j] = 0.f;

    auto load_stage = [&](int t, int st) {
        uint2* As = smem_u2 + st * STG_U2;
        uint2* Bs = As + STG_A;
        #pragma unroll
        for (int i = 0; i < 4; i++) {
            int c = tid + i * 256;
            int m = c >> 3, q = c & 7;
            int gm = rowBase + m;
            bool ok = gm < M;
            const uint2* src = ok ? (A + (size_t)gm * ldp + t * 16 + q * 2) : A;
            cp16(&As[m * ASTP + q * 2], src, ok ? 16 : 0);
        }
        #pragma unroll
        for (int i = 0; i < 4; i++) {
            int c = tid + i * 256;
            int j = c >> 6, q = c & 63;
            int gn = colBase + q * 2;
            bool ok = gn < N;
            const uint2* src = ok ? (B + (size_t)(t * 16 + j) * N + gn) : B;
            cp16(&Bs[j * BSTP + q * 2], src, ok ? 16 : 0);
        }
        asm volatile("cp.async.commit_group;\n");
    };

    load_stage(0, 0);

    for (int t = 0; t < T; t++) {
        const int st = t & 1;
        asm volatile("cp.async.wait_group 0;\n");
        __syncthreads();

        if (t + 1 < T) load_stage(t + 1, st ^ 1);

        const uint2* As = smem_u2 + st * STG_U2;
        const uint2* Bs = As + STG_A;

        #pragma unroll
        for (int ks = 0; ks < 2; ks++) {
            const int kb = ks * 8;
            unsigned ah[4][4], al[4][4], bh[4][2], bl[4][2];
            #pragma unroll
            for (int mi = 0; mi < 4; mi++) {
                int r = wm + mi * 16 + g;
                uint2 p0 = As[r * ASTP + kb + tg];
                uint2 p1 = As[(r + 8) * ASTP + kb + tg];
                uint2 p2 = As[r * ASTP + kb + 4 + tg];
                uint2 p3 = As[(r + 8) * ASTP + kb + 4 + tg];
                ah[mi][0] = p0.x; ah[mi][1] = p1.x; ah[mi][2] = p2.x; ah[mi][3] = p3.x;
                al[mi][0] = p0.y; al[mi][1] = p1.y; al[mi][2] = p2.y; al[mi][3] = p3.y;
            }
            #pragma unroll
            for (int ni = 0; ni < 4; ni++) {
                int n = wn + ni * 8 + g;
                uint2 q0 = Bs[(kb + tg) * BSTP + n];
                uint2 q1 = Bs[(kb + 4 + tg) * BSTP + n];
                bh[ni][0] = q0.x; bh[ni][1] = q1.x;
                bl[ni][0] = q0.y; bl[ni][1] = q1.y;
            }
            #pragma unroll
            for (int mi = 0; mi < 4; mi++)
                #pragma unroll
                for (int ni = 0; ni < 4; ni++) {
                    MMA_BF16(acc[mi][ni], ah[mi], bl[ni]);   // hi*lo
                    MMA_BF16(acc[mi][ni], al[mi], bh[ni]);   // lo*hi
                    MMA_BF16(acc[mi][ni], ah[mi], bh[ni]);   // hi*hi last
                }
        }
    }

    #pragma unroll
    for (int mi = 0; mi < 4; mi++) {
        int r0 = rowBase + wm + mi * 16 + g;
        #pragma unroll
        for (int ni = 0; ni < 4; ni++) {
            int cN = colBase + wn + ni * 8 + tg * 2;
            if (cN >= N) continue;
            #pragma unroll
            for (int half = 0; half < 2; half++) {
                int r = r0 + half * 8;
                if (r >= M) continue;
                size_t idx = (size_t)r * N + cN;
                float2 vv;
                vv.x = acc[mi][ni][half * 2 + 0];
                vv.y = acc[mi][ni][half * 2 + 1];
                if (HAS_ADD) {
                    float2 a = *(const float2*)(Add + idx);
                    vv.x += a.x; vv.y += a.y;
                }
                if (HAS_BIAS) {
                    float2 b = *(const float2*)(bias + cN);
                    vv.x += b.x; vv.y += b.y;
                }
                if (WRITE_RAW) *(float2*)(Craw + idx) = vv;
                if (RELU) { vv.x = fmaxf(vv.x, 0.f); vv.y = fmaxf(vv.y, 0.f); }
                *(float2*)(C + idx) = vv;
            }
        }
    }
}

// ---------------- weight split-pack (2-segment k remap), layout [j][n] ----------------
__global__ void packW_kernel(const float* __restrict__ W, int N, int Jtot,
                             int s0, int l0, int d0, int s1, int l1, int d1,
                             uint2* __restrict__ out)
{
    long tot = (long)Jtot * N;
    for (long idx = (long)blockIdx.x * blockDim.x + threadIdx.x; idx < tot;
         idx += (long)gridDim.x * blockDim.x) {
        int j = (int)(idx / N), n = (int)(idx % N);
        float v[2];
        #pragma unroll
        for (int e = 0; e < 2; e++) {
            int k = 2 * j + e, row = -1;
            if (k >= d1 && k < d1 + l1) row = s1 + (k - d1);
            else if (k >= d0 && k < d0 + l0) row = s0 + (k - d0);
            v[e] = (row < 0) ? 0.f : W[(size_t)row * N + n];
        }
        out[idx] = splitpack(v[0], v[1]);
    }
}

// ---------------- f_atoms -> packed ----------------
__global__ void pack_fa_kernel(const float* __restrict__ fa, uint2* __restrict__ out)
{
    long tot = (long)NA * JP_FA;
    for (long idx = (long)blockIdx.x * blockDim.x + threadIdx.x; idx < tot;
         idx += (long)gridDim.x * blockDim.x) {
        int n = (int)(idx / JP_FA), j = (int)(idx % JP_FA);
        int k0 = 2 * j;
        float v0 = (k0     < FD) ? fa[(size_t)n * FD + k0]     : 0.f;
        float v1 = (k0 + 1 < FD) ? fa[(size_t)n * FD + k0 + 1] : 0.f;
        out[idx] = splitpack(v0, v1);
    }
}

// ---------------- build X packed: rows (n*3+c), K layout [a(134)|self(134)] ----------------
__global__ void build_X_kernel(const float* __restrict__ f_atoms, const float* __restrict__ f_bonds,
                               const int* __restrict__ a2a, const int* __restrict__ a2b,
                               uint2* __restrict__ Xp)
{
    int n = blockIdx.x;
    __shared__ int   nb[KNB];
    __shared__ float bond[KNB][3];
    __shared__ float stg[6][134];
    if (threadIdx.x < KNB) {
        int k = threadIdx.x;
        nb[k] = a2a[n * KNB + k];
        int b = a2b[n * KNB + k];
        bond[k][0] = f_bonds[(size_t)b * 3 + 0];
        bond[k][1] = f_bonds[(size_t)b * 3 + 1];
        bond[k][2] = f_bonds[(size_t)b * 3 + 2];
    }
    if (threadIdx.x < 6) stg[threadIdx.x][133] = 0.f;
    __syncthreads();
    float ms0 = 0.f, ms1 = 0.f, ms2 = 0.f;
    #pragma unroll
    for (int k = 0; k < KNB; k++) {
        float mk = (nb[k] > 0) ? 1.f : 0.f;
        ms0 += mk * bond[k][0];
        ms1 += mk * bond[k][1];
        ms2 += mk * bond[k][2];
    }
    for (int f = threadIdx.x; f < FD; f += blockDim.x) {
        float selfv = f_atoms[(size_t)n * FD + f];
        float a0 = 0.f, a1 = 0.f, a2 = 0.f;
        #pragma unroll
        for (int k = 0; k < KNB; k++) {
            float fv = f_atoms[(size_t)nb[k] * FD + f];
            a0 += fv * bond[k][0];
            a1 += fv * bond[k][1];
            a2 += fv * bond[k][2];
        }
        stg[0][f] = a0; stg[1][f] = a1; stg[2][f] = a2;
        stg[3][f] = selfv * ms0; stg[4][f] = selfv * ms1; stg[5][f] = selfv * ms2;
    }
    __syncthreads();
    for (int t = threadIdx.x; t < 3 * JP_X; t += blockDim.x) {
        int c = t / JP_X, j = t % JP_X;
        float v[2];
        #pragma unroll
        for (int e = 0; e < 2; e++) {
            int k = 2 * j + e;
            if (k < 134)      v[e] = stg[c][k];
            else if (k < 268) v[e] = stg[3 + c][k - 134];
            else              v[e] = 0.f;
        }
        Xp[((size_t)n * 3 + c) * JP_X + j] = splitpack(v[0], v[1]);
    }
}

// ---------------- message-passing gather -> packed (float4 loads; invnorm fused) ----------------
// s rows: 275 float4; v rows: 825 float4 (3 x 275).
__global__ void gather_kernel(const float* __restrict__ s, const float* __restrict__ v,
                              const int* __restrict__ a2a,
                              uint2* __restrict__ sagg_p, uint2* __restrict__ vagg_p)
{
    int n = blockIdx.x;
    __shared__ int nb[KNB];
    if (threadIdx.x < KNB) nb[threadIdx.x] = a2a[n * KNB + threadIdx.x];
    __syncthreads();
    int cnt = 0;
    #pragma unroll
    for (int k = 0; k < KNB; k++) cnt += (nb[k] > 0) ? 1 : 0;
    const float sc = 1.f / (float)max(cnt, 1);

    const float4* s4 = (const float4*)s;
    const float4* v4 = (const float4*)v;
    size_t b0 = (size_t)nb[0] * 275, b1 = (size_t)nb[1] * 275, b2 = (size_t)nb[2] * 275;
    size_t b3 = (size_t)nb[3] * 275, b4 = (size_t)nb[4] * 275, b5 = (size_t)nb[5] * 275;

    // s part: 275 data slots (2 pairs each) + 5 pad slots (pairs 550..559)
    uint2* sd = sagg_p + (size_t)n * JP_H;
    for (int t = threadIdx.x; t < 280; t += blockDim.x) {
        if (t < 275) {
            float4 x0 = s4[b0+t], x1 = s4[b1+t], x2 = s4[b2+t];
            float4 x3 = s4[b3+t], x4 = s4[b4+t], x5 = s4[b5+t];
            float4 a;
            a.x = x0.x + x1.x + x2.x + x3.x + x4.x + x5.x;
            a.y = x0.y + x1.y + x2.y + x3.y + x4.y + x5.y;
            a.z = x0.z + x1.z + x2.z + x3.z + x4.z + x5.z;
            a.w = x0.w + x1.w + x2.w + x3.w + x4.w + x5.w;
            *(uint4*)(sd + 2 * t) = splitpack4(a);
        } else {
            *(uint4*)(sd + 550 + 2 * (t - 275)) = make_uint4(0, 0, 0, 0);
        }
    }
    // v part: per c: 275 data + 5 pad; 3 x 280 = 840 slots
    size_t c0 = b0 * 3, c1 = b1 * 3, c2 = b2 * 3, c3 = b3 * 3, c4 = b4 * 3, c5 = b5 * 3;
    for (int t = threadIdx.x; t < 840; t += blockDim.x) {
        int c = t / 280, u = t % 280;
        uint2* dst = vagg_p + ((size_t)n * 3 + c) * JP_H;
        if (u < 275) {
            size_t e = (size_t)c * 275 + u;
            float4 x0 = v4[c0+e], x1 = v4[c1+e], x2 = v4[c2+e];
            float4 x3 = v4[c3+e], x4 = v4[c4+e], x5 = v4[c5+e];
            float4 a;
            a.x = (x0.x + x1.x + x2.x + x3.x + x4.x + x5.x) * sc;
            a.y = (x0.y + x1.y + x2.y + x3.y + x4.y + x5.y) * sc;
            a.z = (x0.z + x1.z + x2.z + x3.z + x4.z + x5.z) * sc;
            a.w = (x0.w + x1.w + x2.w + x3.w + x4.w + x5.w) * sc;
            *(uint4*)(dst + 2 * u) = splitpack4(a);
        } else {
            *(uint4*)(dst + 550 + 2 * (u - 275)) = make_uint4(0, 0, 0, 0);
        }
    }
}

// ---------------- output-stage concat builders (gather fused, float4) ----------------
// osin row pairs: [0,67) fa | [67,617) gather (float4 loads, uint2 stores) | [617,624) pad
__global__ void build_osin_kernel(const float* __restrict__ fa, const float* __restrict__ s,
                                  const int* __restrict__ a2a, uint2* __restrict__ osin_p)
{
    int n = blockIdx.x;
    __shared__ int nb[KNB];
    if (threadIdx.x < KNB) nb[threadIdx.x] = a2a[n * KNB + threadIdx.x];
    __syncthreads();
    const float4* s4 = (const float4*)s;
    size_t b0 = (size_t)nb[0] * 275, b1 = (size_t)nb[1] * 275, b2 = (size_t)nb[2] * 275;
    size_t b3 = (size_t)nb[3] * 275, b4 = (size_t)nb[4] * 275, b5 = (size_t)nb[5] * 275;
    uint2* dst = osin_p + (size_t)n * JP_OS;
    for (int t = threadIdx.x; t < 67 + 275 + 7; t += blockDim.x) {
        if (t < 67) {
            int k0 = 2 * t;
            float v0 = fa[(size_t)n * FD + k0];
            float v1 = (k0 + 1 < FD) ? fa[(size_t)n * FD + k0 + 1] : 0.f;
            dst[t] = splitpack(v0, v1);
        } else if (t < 342) {
            int w = t - 67;
            float4 x0 = s4[b0+w], x1 = s4[b1+w], x2 = s4[b2+w];
            float4 x3 = s4[b3+w], x4 = s4[b4+w], x5 = s4[b5+w];
            float4 a;
            a.x = x0.x + x1.x + x2.x + x3.x + x4.x + x5.x;
            a.y = x0.y + x1.y + x2.y + x3.y + x4.y + x5.y;
            a.z = x0.z + x1.z + x2.z + x3.z + x4.z + x5.z;
            a.w = x0.w + x1.w + x2.w + x3.w + x4.w + x5.w;
            dst[67 + 2 * w] = splitpack(a.x, a.y);
            dst[68 + 2 * w] = splitpack(a.z, a.w);
        } else {
            dst[617 + (t - 342)] = make_uint2(0, 0);
        }
    }
}

// ovin row (n*3+c) pairs: [0,550) vi | [550,1100) gather | [1100,1104) pad. All float4.
__global__ void build_ovin_kernel(const float* __restrict__ vi, const float* __restrict__ v,
                                  const int* __restrict__ a2a, uint2* __restrict__ ovin_p)
{
    int n = blockIdx.x;
    __shared__ int nb[KNB];
    if (threadIdx.x < KNB) nb[threadIdx.x] = a2a[n * KNB + threadIdx.x];
    __syncthreads();
    const float4* vi4 = (const float4*)vi;
    const float4* v4  = (const float4*)v;
    size_t c0 = (size_t)nb[0] * 825, c1 = (size_t)nb[1] * 825, c2 = (size_t)nb[2] * 825;
    size_t c3 = (size_t)nb[3] * 825, c4 = (size_t)nb[4] * 825, c5 = (size_t)nb[5] * 825;
    for (int t = threadIdx.x; t < 3 * 552; t += blockDim.x) {
        int c = t / 552, u = t % 552;
        uint2* dst = ovin_p + ((size_t)n * 3 + c) * JP_OV;
        if (u < 275) {
            float4 x = vi4[((size_t)n * 3 + c) * 275 + u];
            *(uint4*)(dst + 2 * u) = splitpack4(x);
        } else if (u < 550) {
            int w = u - 275;
            size_t e = (size_t)c * 275 + w;
            float4 x0 = v4[c0+e], x1 = v4[c1+e], x2 = v4[c2+e];
            float4 x3 = v4[c3+e], x4 = v4[c4+e], x5 = v4[c5+e];
            float4 a;
            a.x = x0.x + x1.x + x2.x + x3.x + x4.x + x5.x;
            a.y = x0.y + x1.y + x2.y + x3.y + x4.y + x5.y;
            a.z = x0.z + x1.z + x2.z + x3.z + x4.z + x5.z;
            a.w = x0.w + x1.w + x2.w + x3.w + x4.w + x5.w;
            *(uint4*)(dst + 550 + 2 * w) = splitpack4(a);
        } else {
            *(uint4*)(dst + 1100 + 2 * (u - 550)) = make_uint4(0, 0, 0, 0);
        }
    }
}

// o[n] = [osb | sum_c ovb], float4
__global__ void build_o_kernel(const float* __restrict__ osb, const float* __restrict__ ovb,
                               float* __restrict__ o)
{
    const float4* osb4 = (const float4*)osb;   // row 175
    const float4* ovb4 = (const float4*)ovb;   // row 525 (3 x 175)
    float4* o4 = (float4*)o;                   // row 350
    long tot = (long)NA * 350;
    for (long idx = (long)blockIdx.x * blockDim.x + threadIdx.x; idx < tot;
         idx += (long)gridDim.x * blockDim.x) {
        int n = (int)(idx / 350);
        int j = (int)(idx % 350);
        float4 r;
        if (j < 175) {
            r = osb4[(size_t)n * 175 + j];
        } else {
            size_t b = (size_t)n * 525 + (j - 175);
            float4 x0 = ovb4[b], x1 = ovb4[b + 175], x2 = ovb4[b + 350];
            r.x = x0.x + x1.x + x2.x;
            r.y = x0.y + x1.y + x2.y;
            r.z = x0.z + x1.z + x2.z;
            r.w = x0.w + x1.w + x2.w;
        }
        o4[idx] = r;
    }
}

// ---------------- readout ----------------
__global__ void mol_start_kernel(const int* __restrict__ ids, int* __restrict__ start)
{
    int m = blockIdx.x * blockDim.x + threadIdx.x;
    if (m > NM) return;
    int lo = 0, hi = NA;
    while (lo < hi) {
        int mid = (lo + hi) >> 1;
        if (ids[mid] < m) lo = mid + 1; else hi = mid;
    }
    start[m] = lo;
}

__global__ void segment_mean_kernel(const float* __restrict__ o, const int* __restrict__ start,
                                    uint2* __restrict__ mol_p)
{
    int m = blockIdx.x;
    int s0 = start[m], e0 = start[m + 1];
    int cnt = e0 - s0;
    if (s0 == 0 && e0 > 0) cnt -= 1;   // atom 0 is padding
    float sc = 1.f / (float)max(cnt, 1);
    const float4* o4 = (const float4*)o;   // row 350
    uint2* dst = mol_p + (size_t)m * JP_FF;
    for (int t = threadIdx.x; t < 352; t += blockDim.x) {
        if (t < 350) {
            float4 a = make_float4(0.f, 0.f, 0.f, 0.f);
            for (int n = s0; n < e0; n++) {
                if (n == 0) continue;
                float4 x = o4[(size_t)n * 350 + t];
                a.x += x.x; a.y += x.y; a.z += x.z; a.w += x.w;
            }
            a.x *= sc; a.y *= sc; a.z *= sc; a.w *= sc;
            *(uint4*)(dst + 2 * t) = splitpack4(a);
        } else {
            *(uint4*)(dst + 700 + 2 * (t - 350)) = make_uint4(0, 0, 0, 0);
        }
    }
}

__global__ void ffn_out_kernel(const float* __restrict__ h, const float* __restrict__ W2,
                               const float* __restrict__ b2, float* __restrict__ out)
{
    int m = blockIdx.x;
    float acc = 0.f;
    for (int j = threadIdx.x; j < FHD; j += 256) acc += h[m * FHD + j] * W2[j];
    __shared__ float red[256];
    red[threadIdx.x] = acc;
    __syncthreads();
    for (int st = 128; st > 0; st >>= 1) {
        if (threadIdx.x < st) red[threadIdx.x] += red[threadIdx.x + st];
        __syncthreads();
    }
    if (threadIdx.x == 0) out[m] = red[0] + b2[0];
}

// ---------------- launch ----------------
extern "C" void kernel_launch(void* const* d_in, const int* in_sizes, int n_in,
                              void* d_out, int out_size)
{
    const float* f_atoms = (const float*)d_in[0];
    const float* f_bonds = (const float*)d_in[1];
    const float* W_is    = (const float*)d_in[2];
    const float* W_iv    = (const float*)d_in[3];
    const float* W_hs    = (const float*)d_in[4];
    const float* W_hv    = (const float*)d_in[5];
    const float* W_os    = (const float*)d_in[6];
    const float* b_os    = (const float*)d_in[7];
    const float* W_ov    = (const float*)d_in[8];
    const float* b_ov    = (const float*)d_in[9];
    const float* ffn_W1  = (const float*)d_in[10];
    const float* ffn_b1  = (const float*)d_in[11];
    const float* ffn_W2  = (const float*)d_in[12];
    const float* ffn_b2  = (const float*)d_in[13];
    const int*   a2a     = (const int*)d_in[14];
    const int*   a2b     = (const int*)d_in[15];
    const int*   mol_ids = (const int*)d_in[16];
    float*       out     = (float*)d_out;

    uint2 *p_fa, *p_X, *p_sagg, *p_vagg, *p_osin, *p_ovin, *p_mol;
    uint2 *p_Wis, *p_Wiv, *p_Whs, *p_Whv, *p_Wos, *p_Wov, *p_Wff;
    float *p_si, *p_s, *p_vi, *p_v, *p_osb, *p_ovb, *p_o, *p_h;
    int* p_molstart;
    cudaGetSymbolAddress((void**)&p_fa,   g_fa_p);
    cudaGetSymbolAddress((void**)&p_X,    g_X_p);
    cudaGetSymbolAddress((void**)&p_sagg, g_sagg_p);
    cudaGetSymbolAddress((void**)&p_vagg, g_vagg_p);
    cudaGetSymbolAddress((void**)&p_osin, g_osin_p);
    cudaGetSymbolAddress((void**)&p_ovin, g_ovin_p);
    cudaGetSymbolAddress((void**)&p_mol,  g_mol_p);
    cudaGetSymbolAddress((void**)&p_Wis,  g_Wis_p);
    cudaGetSymbolAddress((void**)&p_Wiv,  g_Wiv_p);
    cudaGetSymbolAddress((void**)&p_Whs,  g_Whs_p);
    cudaGetSymbolAddress((void**)&p_Whv,  g_Whv_p);
    cudaGetSymbolAddress((void**)&p_Wos,  g_Wos_p);
    cudaGetSymbolAddress((void**)&p_Wov,  g_Wov_p);
    cudaGetSymbolAddress((void**)&p_Wff,  g_Wff_p);
    cudaGetSymbolAddress((void**)&p_si,   g_si);
    cudaGetSymbolAddress((void**)&p_s,    g_s);
    cudaGetSymbolAddress((void**)&p_vi,   g_vi);
    cudaGetSymbolAddress((void**)&p_v,    g_v);
    cudaGetSymbolAddress((void**)&p_osb,  g_osb);
    cudaGetSymbolAddress((void**)&p_ovb,  g_ovb);
    cudaGetSymbolAddress((void**)&p_o,    g_o);
    cudaGetSymbolAddress((void**)&p_h,    g_h);
    cudaGetSymbolAddress((void**)&p_molstart, g_molstart);

    cudaFuncSetAttribute(bgemm_kernel<true,false,false,true>,
                         cudaFuncAttributeMaxDynamicSharedMemorySize, SMEM_GEMM);
    cudaFuncSetAttribute(bgemm_kernel<true,true,false,false>,
                         cudaFuncAttributeMaxDynamicSharedMemorySize, SMEM_GEMM);
    cudaFuncSetAttribute(bgemm_kernel<true,false,true,false>,
                         cudaFuncAttributeMaxDynamicSharedMemorySize, SMEM_GEMM);

    // 0. weight packing
    packW_kernel<<<512, 256>>>(W_is, HD, JP_FA, 0, 133, 0, 0, 0, 0, p_Wis);
    packW_kernel<<<512, 256>>>(W_iv, HD, JP_X, 0, 133, 0, 133, 133, 134, p_Wiv);
    packW_kernel<<<1024, 256>>>(W_hs, HD, JP_H, 0, 1100, 0, 0, 0, 0, p_Whs);
    packW_kernel<<<1024, 256>>>(W_hv, HD, JP_H, 0, 1100, 0, 0, 0, 0, p_Whv);
    packW_kernel<<<1024, 256>>>(W_os, FHD, JP_OS, 0, 133, 0, 133, 1100, 134, p_Wos);
    packW_kernel<<<1024, 256>>>(W_ov, FHD, JP_OV, 0, 2200, 0, 0, 0, 0, p_Wov);
    packW_kernel<<<1024, 256>>>(ffn_W1, FHD, JP_FF, 0, 1400, 0, 0, 0, 0, p_Wff);

    // 1. prep
    pack_fa_kernel<<<2048, 256>>>(f_atoms, p_fa);
    build_X_kernel<<<NA, 192>>>(f_atoms, f_bonds, a2a, a2b, p_X);

    // 2. si = f_atoms @ W_is
    dim3 gsi((HD + 127) / 128, (NA + 127) / 128);
    bgemm_kernel<true, false, false, true><<<gsi, 256, SMEM_GEMM>>>(
        p_fa, p_Wis, nullptr, nullptr, p_s, p_si, NA, HD, 5, JP_FA);

    // 3. vi = X @ W_iv
    dim3 gvi((HD + 127) / 128, (3 * NA + 127) / 128);
    bgemm_kernel<true, false, false, true><<<gvi, 256, SMEM_GEMM>>>(
        p_X, p_Wiv, nullptr, nullptr, p_v, p_vi, 3 * NA, HD, 9, JP_X);

    // 4. message passing
    for (int it = 0; it < 6; it++) {
        gather_kernel<<<NA, 256>>>(p_s, p_v, a2a, p_sagg, p_vagg);
        bgemm_kernel<true, true, false, false><<<gsi, 256, SMEM_GEMM>>>(
            p_sagg, p_Whs, p_si, nullptr, p_s, nullptr, NA, HD, 35, JP_H);
        bgemm_kernel<true, true, false, false><<<gvi, 256, SMEM_GEMM>>>(
            p_vagg, p_Whv, p_vi, nullptr, p_v, nullptr, 3 * NA, HD, 35, JP_H);
    }

    // 5. output stage (gathers fused into concat builders)
    build_osin_kernel<<<NA, 256>>>(f_atoms, p_s, a2a, p_osin);
    build_ovin_kernel<<<NA, 256>>>(p_vi, p_v, a2a, p_ovin);
    dim3 gos((FHD + 127) / 128, (NA + 127) / 128);
    bgemm_kernel<true, false, true, false><<<gos, 256, SMEM_GEMM>>>(
        p_osin, p_Wos, nullptr, b_os, p_osb, nullptr, NA, FHD, 39, JP_OS);
    dim3 gov((FHD + 127) / 128, (3 * NA + 127) / 128);
    bgemm_kernel<true, false, true, false><<<gov, 256, SMEM_GEMM>>>(
        p_ovin, p_Wov, nullptr, b_ov, p_ovb, nullptr, 3 * NA, FHD, 69, JP_OV);
    {
        long tot3 = (long)NA * 350;
        build_o_kernel<<<(unsigned)((tot3 + 255) / 256), 256>>>(p_osb, p_ovb, p_o);
    }

    // 6. readout + FFN
    mol_start_kernel<<<4, 256>>>(mol_ids, p_molstart);
    segment_mean_kernel<<<NM, 256>>>(p_o, p_molstart, p_mol);
    dim3 gff((FHD + 127) / 128, (NM + 127) / 128);
    bgemm_kernel<true, false, true, false><<<gff, 256, SMEM_GEMM>>>(
        p_mol, p_Wff, nullptr, ffn_b1, p_h, nullptr, NM, FHD, 44, JP_FF);
    ffn_out_kernel<<<NM, 256>>>(p_h, ffn_W2, ffn_b2, out);
}

// round 13
// speedup vs baseline: 1.1324x; 1.0112x over previous
#include <cuda_runtime.h>
#include <cstdint>

// ---------------- Problem constants ----------------
#define NA   20001
#define FD   133
#define KNB  6
#define HD   1100
#define FHD  700
#define NM   800
#define FFK  1400

// K paddings in PAIRS (bf16x2). Multiples of 16 pairs = 32 elems (one stage).
#define JP_FA   80      // si : T=5
#define JP_X    144     // vi : T=9
#define JP_H    560     // hs/hv : T=35
#define JP_OS   624     // os : T=39
#define JP_OV   1104    // ov : T=69
#define JP_FF   704     // ffn : T=44

// ---------------- Scratch (device globals) ----------------
__device__ __align__(16) uint2 g_fa_p  [(size_t)NA * JP_FA];
__device__ __align__(16) uint2 g_X_p   [(size_t)NA * 3 * JP_X];
__device__ __align__(16) uint2 g_sagg_p[(size_t)NA * JP_H];
__device__ __align__(16) uint2 g_vagg_p[(size_t)NA * 3 * JP_H];
__device__ __align__(16) uint2 g_osin_p[(size_t)NA * JP_OS];
__device__ __align__(16) uint2 g_ovin_p[(size_t)NA * 3 * JP_OV];
__device__ __align__(16) uint2 g_mol_p [(size_t)NM * JP_FF];

__device__ __align__(16) uint2 g_Wis_p [(size_t)JP_FA * HD];
__device__ __align__(16) uint2 g_Wiv_p [(size_t)JP_X  * HD];
__device__ __align__(16) uint2 g_Whs_p [(size_t)JP_H  * HD];
__device__ __align__(16) uint2 g_Whv_p [(size_t)JP_H  * HD];
__device__ __align__(16) uint2 g_Wos_p [(size_t)JP_OS * FHD];
__device__ __align__(16) uint2 g_Wov_p [(size_t)JP_OV * FHD];
__device__ __align__(16) uint2 g_Wff_p [(size_t)JP_FF * FHD];

__device__ __align__(16) float g_si [(size_t)NA * HD];
__device__ __align__(16) float g_s  [(size_t)NA * HD];
__device__ __align__(16) float g_vi [(size_t)NA * 3 * HD];
__device__ __align__(16) float g_v  [(size_t)NA * 3 * HD];
__device__ __align__(16) float g_osb[(size_t)NA * FHD];
__device__ __align__(16) float g_ovb[(size_t)NA * 3 * FHD];
__device__ __align__(16) float g_o  [(size_t)NA * FFK];
__device__ __align__(16) float g_h  [NM * FHD];
__device__ int g_molstart[NM + 1];

// ---------------- bf16 split-pack helper ----------------
__device__ __forceinline__ uint2 splitpack(float x0, float x1) {
    unsigned h;
    asm("cvt.rn.bf16x2.f32 %0, %1, %2;" : "=r"(h) : "f"(x1), "f"(x0));
    float h0 = __uint_as_float(h << 16);
    float h1 = __uint_as_float(h & 0xFFFF0000u);
    unsigned l;
    asm("cvt.rn.bf16x2.f32 %0, %1, %2;" : "=r"(l) : "f"(x1 - h1), "f"(x0 - h0));
    return make_uint2(h, l);
}

__device__ __forceinline__ uint4 splitpack4(float4 a) {
    uint2 r0 = splitpack(a.x, a.y);
    uint2 r1 = splitpack(a.z, a.w);
    return make_uint4(r0.x, r0.y, r1.x, r1.y);
}

__device__ __forceinline__ void cp16(void* dst_smem, const void* src, int bytes) {
    unsigned sa = (unsigned)__cvta_generic_to_shared(dst_smem);
    asm volatile("cp.async.ca.shared.global [%0], [%1], 16, %2;\n"
                 :: "r"(sa), "l"(src), "r"(bytes));
}

#define MMA_BF16(ACC, AF, BF)                                                   \
    asm volatile(                                                               \
        "mma.sync.aligned.m16n8k16.row.col.f32.bf16.bf16.f32 "                  \
        "{%0,%1,%2,%3}, {%4,%5,%6,%7}, {%8,%9}, {%0,%1,%2,%3};\n"               \
        : "+f"(ACC[0]), "+f"(ACC[1]), "+f"(ACC[2]), "+f"(ACC[3])                \
        : "r"(AF[0]), "r"(AF[1]), "r"(AF[2]), "r"(AF[3]),                       \
          "r"(BF[0]), "r"(BF[1]))

// ---------------- bf16x3 dual-problem GEMM ----------------
// blockIdx.y < tiles0 -> problem 0, else problem 1 (row tile (y - tiles0)).
// Per problem: C = act(A@B [+Add] [+bias]). BK=32/stage, double-buffered,
// one __syncthreads per stage (load for t+1 issued after the barrier).
#define ASTP 18
#define BSTP 132
#define STG_A (128 * ASTP)            // uint2
#define STG_B (16 * BSTP)             // uint2
#define STG_U2 (STG_A + STG_B)        // 4416 uint2 = 35328 B
#define SMEM_GEMM (2 * STG_U2 * 8)    // 70656 B

template<bool RELU, bool HAS_ADD, bool HAS_BIAS, bool WRITE_RAW>
__global__ __launch_bounds__(256, 2)
void bgemm_kernel(const uint2* __restrict__ A0, const uint2* __restrict__ B0,
                  const float* __restrict__ Add0, const float* __restrict__ bias0,
                  float* __restrict__ C0, float* __restrict__ Craw0,
                  int M0, int T0, int ldp0,
                  const uint2* __restrict__ A1, const uint2* __restrict__ B1,
                  const float* __restrict__ Add1, const float* __restrict__ bias1,
                  float* __restrict__ C1, float* __restrict__ Craw1,
                  int M1, int T1, int ldp1,
                  int N, int tiles0)
{
    extern __shared__ __align__(16) uint2 smem_u2[];

    const bool p1 = (int)blockIdx.y >= tiles0;
    const uint2* __restrict__ A   = p1 ? A1   : A0;
    const uint2* __restrict__ B   = p1 ? B1   : B0;
    const float* __restrict__ Add = p1 ? Add1 : Add0;
    const float* __restrict__ bias= p1 ? bias1: bias0;
    float* __restrict__ C    = p1 ? C1    : C0;
    float* __restrict__ Craw = p1 ? Craw1 : Craw0;
    const int M   = p1 ? M1   : M0;
    const int T   = p1 ? T1   : T0;
    const int ldp = p1 ? ldp1 : ldp0;
    const int rowBase = (p1 ? ((int)blockIdx.y - tiles0) : (int)blockIdx.y) * 128;

    const int tid = threadIdx.x;
    const int colBase = blockIdx.x * 128;
    const int warpId = tid >> 5;
    const int lane = tid & 31;
    const int g  = lane >> 2;
    const int tg = lane & 3;
    const int wm = (warpId & 1) * 64;
    const int wn = (warpId >> 1) * 32;

    float acc[4][4][4];
    #pragma unroll
    for (int mi = 0; mi < 4; mi++)
        #pragma unroll
        for (int ni = 0; ni < 4; ni++)
            #pragma unroll
            for (int j = 0; j < 4; j++) acc[mi][ni][j] = 0.f;

    auto load_stage = [&](int t, int st) {
        uint2* As = smem_u2 + st * STG_U2;
        uint2* Bs = As + STG_A;
        #pragma unroll
        for (int i = 0; i < 4; i++) {
            int c = tid + i * 256;
            int m = c >> 3, q = c & 7;
            int gm = rowBase + m;
            bool ok = gm < M;
            const uint2* src = ok ? (A + (size_t)gm * ldp + t * 16 + q * 2) : A;
            cp16(&As[m * ASTP + q * 2], src, ok ? 16 : 0);
        }
        #pragma unroll
        for (int i = 0; i < 4; i++) {
            int c = tid + i * 256;
            int j = c >> 6, q = c & 63;
            int gn = colBase + q * 2;
            bool ok = gn < N;
            const uint2* src = ok ? (B + (size_t)(t * 16 + j) * N + gn) : B;
            cp16(&Bs[j * BSTP + q * 2], src, ok ? 16 : 0);
        }
        asm volatile("cp.async.commit_group;\n");
    };

    load_stage(0, 0);

    for (int t = 0; t < T; t++) {
        const int st = t & 1;
        asm volatile("cp.async.wait_group 0;\n");
        __syncthreads();

        if (t + 1 < T) load_stage(t + 1, st ^ 1);

        const uint2* As = smem_u2 + st * STG_U2;
        const uint2* Bs = As + STG_A;

        #pragma unroll
        for (int ks = 0; ks < 2; ks++) {
            const int kb = ks * 8;
            unsigned ah[4][4], al[4][4], bh[4][2], bl[4][2];
            #pragma unroll
            for (int mi = 0; mi < 4; mi++) {
                int r = wm + mi * 16 + g;
                uint2 p0 = As[r * ASTP + kb + tg];
                uint2 q1 = As[(r + 8) * ASTP + kb + tg];
                uint2 p2 = As[r * ASTP + kb + 4 + tg];
                uint2 p3 = As[(r + 8) * ASTP + kb + 4 + tg];
                ah[mi][0] = p0.x; ah[mi][1] = q1.x; ah[mi][2] = p2.x; ah[mi][3] = p3.x;
                al[mi][0] = p0.y; al[mi][1] = q1.y; al[mi][2] = p2.y; al[mi][3] = p3.y;
            }
            #pragma unroll
            for (int ni = 0; ni < 4; ni++) {
                int n = wn + ni * 8 + g;
                uint2 q0 = Bs[(kb + tg) * BSTP + n];
                uint2 q1 = Bs[(kb + 4 + tg) * BSTP + n];
                bh[ni][0] = q0.x; bh[ni][1] = q1.x;
                bl[ni][0] = q0.y; bl[ni][1] = q1.y;
            }
            #pragma unroll
            for (int mi = 0; mi < 4; mi++)
                #pragma unroll
                for (int ni = 0; ni < 4; ni++) {
                    MMA_BF16(acc[mi][ni], ah[mi], bl[ni]);   // hi*lo
                    MMA_BF16(acc[mi][ni], al[mi], bh[ni]);   // lo*hi
                    MMA_BF16(acc[mi][ni], ah[mi], bh[ni]);   // hi*hi last
                }
        }
    }

    #pragma unroll
    for (int mi = 0; mi < 4; mi++) {
        int r0 = rowBase + wm + mi * 16 + g;
        #pragma unroll
        for (int ni = 0; ni < 4; ni++) {
            int cN = colBase + wn + ni * 8 + tg * 2;
            if (cN >= N) continue;
            #pragma unroll
            for (int half = 0; half < 2; half++) {
                int r = r0 + half * 8;
                if (r >= M) continue;
                size_t idx = (size_t)r * N + cN;
                float2 vv;
                vv.x = acc[mi][ni][half * 2 + 0];
                vv.y = acc[mi][ni][half * 2 + 1];
                if (HAS_ADD) {
                    float2 a = *(const float2*)(Add + idx);
                    vv.x += a.x; vv.y += a.y;
                }
                if (HAS_BIAS) {
                    float2 b = *(const float2*)(bias + cN);
                    vv.x += b.x; vv.y += b.y;
                }
                if (WRITE_RAW) *(float2*)(Craw + idx) = vv;
                if (RELU) { vv.x = fmaxf(vv.x, 0.f); vv.y = fmaxf(vv.y, 0.f); }
                *(float2*)(C + idx) = vv;
            }
        }
    }
}

// ---------------- weight split-pack (2-segment k remap), layout [j][n] ----------------
__global__ void packW_kernel(const float* __restrict__ W, int N, int Jtot,
                             int s0, int l0, int d0, int s1, int l1, int d1,
                             uint2* __restrict__ out)
{
    long tot = (long)Jtot * N;
    for (long idx = (long)blockIdx.x * blockDim.x + threadIdx.x; idx < tot;
         idx += (long)gridDim.x * blockDim.x) {
        int j = (int)(idx / N), n = (int)(idx % N);
        float v[2];
        #pragma unroll
        for (int e = 0; e < 2; e++) {
            int k = 2 * j + e, row = -1;
            if (k >= d1 && k < d1 + l1) row = s1 + (k - d1);
            else if (k >= d0 && k < d0 + l0) row = s0 + (k - d0);
            v[e] = (row < 0) ? 0.f : W[(size_t)row * N + n];
        }
        out[idx] = splitpack(v[0], v[1]);
    }
}

// ---------------- f_atoms -> packed ----------------
__global__ void pack_fa_kernel(const float* __restrict__ fa, uint2* __restrict__ out)
{
    long tot = (long)NA * JP_FA;
    for (long idx = (long)blockIdx.x * blockDim.x + threadIdx.x; idx < tot;
         idx += (long)gridDim.x * blockDim.x) {
        int n = (int)(idx / JP_FA), j = (int)(idx % JP_FA);
        int k0 = 2 * j;
        float v0 = (k0     < FD) ? fa[(size_t)n * FD + k0]     : 0.f;
        float v1 = (k0 + 1 < FD) ? fa[(size_t)n * FD + k0 + 1] : 0.f;
        out[idx] = splitpack(v0, v1);
    }
}

// ---------------- build X packed: rows (n*3+c), K layout [a(134)|self(134)] ----------------
__global__ void build_X_kernel(const float* __restrict__ f_atoms, const float* __restrict__ f_bonds,
                               const int* __restrict__ a2a, const int* __restrict__ a2b,
                               uint2* __restrict__ Xp)
{
    int n = blockIdx.x;
    __shared__ int   nb[KNB];
    __shared__ float bond[KNB][3];
    __shared__ float stg[6][134];
    if (threadIdx.x < KNB) {
        int k = threadIdx.x;
        nb[k] = a2a[n * KNB + k];
        int b = a2b[n * KNB + k];
        bond[k][0] = f_bonds[(size_t)b * 3 + 0];
        bond[k][1] = f_bonds[(size_t)b * 3 + 1];
        bond[k][2] = f_bonds[(size_t)b * 3 + 2];
    }
    if (threadIdx.x < 6) stg[threadIdx.x][133] = 0.f;
    __syncthreads();
    float ms0 = 0.f, ms1 = 0.f, ms2 = 0.f;
    #pragma unroll
    for (int k = 0; k < KNB; k++) {
        float mk = (nb[k] > 0) ? 1.f : 0.f;
        ms0 += mk * bond[k][0];
        ms1 += mk * bond[k][1];
        ms2 += mk * bond[k][2];
    }
    for (int f = threadIdx.x; f < FD; f += blockDim.x) {
        float selfv = f_atoms[(size_t)n * FD + f];
        float a0 = 0.f, a1 = 0.f, a2 = 0.f;
        #pragma unroll
        for (int k = 0; k < KNB; k++) {
            float fv = f_atoms[(size_t)nb[k] * FD + f];
            a0 += fv * bond[k][0];
            a1 += fv * bond[k][1];
            a2 += fv * bond[k][2];
        }
        stg[0][f] = a0; stg[1][f] = a1; stg[2][f] = a2;
        stg[3][f] = selfv * ms0; stg[4][f] = selfv * ms1; stg[5][f] = selfv * ms2;
    }
    __syncthreads();
    for (int t = threadIdx.x; t < 3 * JP_X; t += blockDim.x) {
        int c = t / JP_X, j = t % JP_X;
        float v[2];
        #pragma unroll
        for (int e = 0; e < 2; e++) {
            int k = 2 * j + e;
            if (k < 134)      v[e] = stg[c][k];
            else if (k < 268) v[e] = stg[3 + c][k - 134];
            else              v[e] = 0.f;
        }
        Xp[((size_t)n * 3 + c) * JP_X + j] = splitpack(v[0], v[1]);
    }
}

// ---------------- message-passing gather -> packed (float4 loads; invnorm fused) ----------------
__global__ void gather_kernel(const float* __restrict__ s, const float* __restrict__ v,
                              const int* __restrict__ a2a,
                              uint2* __restrict__ sagg_p, uint2* __restrict__ vagg_p)
{
    int n = blockIdx.x;
    __shared__ int nb[KNB];
    if (threadIdx.x < KNB) nb[threadIdx.x] = a2a[n * KNB + threadIdx.x];
    __syncthreads();
    int cnt = 0;
    #pragma unroll
    for (int k = 0; k < KNB; k++) cnt += (nb[k] > 0) ? 1 : 0;
    const float sc = 1.f / (float)max(cnt, 1);

    const float4* s4 = (const float4*)s;
    const float4* v4 = (const float4*)v;
    size_t b0 = (size_t)nb[0] * 275, b1 = (size_t)nb[1] * 275, b2 = (size_t)nb[2] * 275;
    size_t b3 = (size_t)nb[3] * 275, b4 = (size_t)nb[4] * 275, b5 = (size_t)nb[5] * 275;

    uint2* sd = sagg_p + (size_t)n * JP_H;
    for (int t = threadIdx.x; t < 280; t += blockDim.x) {
        if (t < 275) {
            float4 x0 = s4[b0+t], x1 = s4[b1+t], x2 = s4[b2+t];
            float4 x3 = s4[b3+t], x4 = s4[b4+t], x5 = s4[b5+t];
            float4 a;
            a.x = x0.x + x1.x + x2.x + x3.x + x4.x + x5.x;
            a.y = x0.y + x1.y + x2.y + x3.y + x4.y + x5.y;
            a.z = x0.z + x1.z + x2.z + x3.z + x4.z + x5.z;
            a.w = x0.w + x1.w + x2.w + x3.w + x4.w + x5.w;
            *(uint4*)(sd + 2 * t) = splitpack4(a);
        } else {
            *(uint4*)(sd + 550 + 2 * (t - 275)) = make_uint4(0, 0, 0, 0);
        }
    }
    size_t c0 = b0 * 3, c1 = b1 * 3, c2 = b2 * 3, c3 = b3 * 3, c4 = b4 * 3, c5 = b5 * 3;
    for (int t = threadIdx.x; t < 840; t += blockDim.x) {
        int c = t / 280, u = t % 280;
        uint2* dst = vagg_p + ((size_t)n * 3 + c) * JP_H;
        if (u < 275) {
            size_t e = (size_t)c * 275 + u;
            float4 x0 = v4[c0+e], x1 = v4[c1+e], x2 = v4[c2+e];
            float4 x3 = v4[c3+e], x4 = v4[c4+e], x5 = v4[c5+e];
            float4 a;
            a.x = (x0.x + x1.x + x2.x + x3.x + x4.x + x5.x) * sc;
            a.y = (x0.y + x1.y + x2.y + x3.y + x4.y + x5.y) * sc;
            a.z = (x0.z + x1.z + x2.z + x3.z + x4.z + x5.z) * sc;
            a.w = (x0.w + x1.w + x2.w + x3.w + x4.w + x5.w) * sc;
            *(uint4*)(dst + 2 * u) = splitpack4(a);
        } else {
            *(uint4*)(dst + 550 + 2 * (u - 275)) = make_uint4(0, 0, 0, 0);
        }
    }
}

// ---------------- output-stage concat builders (gather fused, float4) ----------------
__global__ void build_osin_kernel(const float* __restrict__ fa, const float* __restrict__ s,
                                  const int* __restrict__ a2a, uint2* __restrict__ osin_p)
{
    int n = blockIdx.x;
    __shared__ int nb[KNB];
    if (threadIdx.x < KNB) nb[threadIdx.x] = a2a[n * KNB + threadIdx.x];
    __syncthreads();
    const float4* s4 = (const float4*)s;
    size_t b0 = (size_t)nb[0] * 275, b1 = (size_t)nb[1] * 275, b2 = (size_t)nb[2] * 275;
    size_t b3 = (size_t)nb[3] * 275, b4 = (size_t)nb[4] * 275, b5 = (size_t)nb[5] * 275;
    uint2* dst = osin_p + (size_t)n * JP_OS;
    for (int t = threadIdx.x; t < 67 + 275 + 7; t += blockDim.x) {
        if (t < 67) {
            int k0 = 2 * t;
            float v0 = fa[(size_t)n * FD + k0];
            float v1 = (k0 + 1 < FD) ? fa[(size_t)n * FD + k0 + 1] : 0.f;
            dst[t] = splitpack(v0, v1);
        } else if (t < 342) {
            int w = t - 67;
            float4 x0 = s4[b0+w], x1 = s4[b1+w], x2 = s4[b2+w];
            float4 x3 = s4[b3+w], x4 = s4[b4+w], x5 = s4[b5+w];
            float4 a;
            a.x = x0.x + x1.x + x2.x + x3.x + x4.x + x5.x;
            a.y = x0.y + x1.y + x2.y + x3.y + x4.y + x5.y;
            a.z = x0.z + x1.z + x2.z + x3.z + x4.z + x5.z;
            a.w = x0.w + x1.w + x2.w + x3.w + x4.w + x5.w;
            dst[67 + 2 * w] = splitpack(a.x, a.y);
            dst[68 + 2 * w] = splitpack(a.z, a.w);
        } else {
            dst[617 + (t - 342)] = make_uint2(0, 0);
        }
    }
}

__global__ void build_ovin_kernel(const float* __restrict__ vi, const float* __restrict__ v,
                                  const int* __restrict__ a2a, uint2* __restrict__ ovin_p)
{
    int n = blockIdx.x;
    __shared__ int nb[KNB];
    if (threadIdx.x < KNB) nb[threadIdx.x] = a2a[n * KNB + threadIdx.x];
    __syncthreads();
    const float4* vi4 = (const float4*)vi;
    const float4* v4  = (const float4*)v;
    size_t c0 = (size_t)nb[0] * 825, c1 = (size_t)nb[1] * 825, c2 = (size_t)nb[2] * 825;
    size_t c3 = (size_t)nb[3] * 825, c4 = (size_t)nb[4] * 825, c5 = (size_t)nb[5] * 825;
    for (int t = threadIdx.x; t < 3 * 552; t += blockDim.x) {
        int c = t / 552, u = t % 552;
        uint2* dst = ovin_p + ((size_t)n * 3 + c) * JP_OV;
        if (u < 275) {
            float4 x = vi4[((size_t)n * 3 + c) * 275 + u];
            *(uint4*)(dst + 2 * u) = splitpack4(x);
        } else if (u < 550) {
            int w = u - 275;
            size_t e = (size_t)c * 275 + w;
            float4 x0 = v4[c0+e], x1 = v4[c1+e], x2 = v4[c2+e];
            float4 x3 = v4[c3+e], x4 = v4[c4+e], x5 = v4[c5+e];
            float4 a;
            a.x = x0.x + x1.x + x2.x + x3.x + x4.x + x5.x;
            a.y = x0.y + x1.y + x2.y + x3.y + x4.y + x5.y;
            a.z = x0.z + x1.z + x2.z + x3.z + x4.z + x5.z;
            a.w = x0.w + x1.w + x2.w + x3.w + x4.w + x5.w;
            *(uint4*)(dst + 550 + 2 * w) = splitpack4(a);
        } else {
            *(uint4*)(dst + 1100 + 2 * (u - 550)) = make_uint4(0, 0, 0, 0);
        }
    }
}

// o[n] = [osb | sum_c ovb], float4
__global__ void build_o_kernel(const float* __restrict__ osb, const float* __restrict__ ovb,
                               float* __restrict__ o)
{
    const float4* osb4 = (const float4*)osb;   // row 175
    const float4* ovb4 = (const float4*)ovb;   // row 525
    float4* o4 = (float4*)o;                   // row 350
    long tot = (long)NA * 350;
    for (long idx = (long)blockIdx.x * blockDim.x + threadIdx.x; idx < tot;
         idx += (long)gridDim.x * blockDim.x) {
        int n = (int)(idx / 350);
        int j = (int)(idx % 350);
        float4 r;
        if (j < 175) {
            r = osb4[(size_t)n * 175 + j];
        } else {
            size_t b = (size_t)n * 525 + (j - 175);
            float4 x0 = ovb4[b], x1 = ovb4[b + 175], x2 = ovb4[b + 350];
            r.x = x0.x + x1.x + x2.x;
            r.y = x0.y + x1.y + x2.y;
            r.z = x0.z + x1.z + x2.z;
            r.w = x0.w + x1.w + x2.w;
        }
        o4[idx] = r;
    }
}

// ---------------- readout ----------------
__global__ void mol_start_kernel(const int* __restrict__ ids, int* __restrict__ start)
{
    int m = blockIdx.x * blockDim.x + threadIdx.x;
    if (m > NM) return;
    int lo = 0, hi = NA;
    while (lo < hi) {
        int mid = (lo + hi) >> 1;
        if (ids[mid] < m) lo = mid + 1; else hi = mid;
    }
    start[m] = lo;
}

__global__ void segment_mean_kernel(const float* __restrict__ o, const int* __restrict__ start,
                                    uint2* __restrict__ mol_p)
{
    int m = blockIdx.x;
    int s0 = start[m], e0 = start[m + 1];
    int cnt = e0 - s0;
    if (s0 == 0 && e0 > 0) cnt -= 1;   // atom 0 is padding
    float sc = 1.f / (float)max(cnt, 1);
    const float4* o4 = (const float4*)o;
    uint2* dst = mol_p + (size_t)m * JP_FF;
    for (int t = threadIdx.x; t < 352; t += blockDim.x) {
        if (t < 350) {
            float4 a = make_float4(0.f, 0.f, 0.f, 0.f);
            for (int n = s0; n < e0; n++) {
                if (n == 0) continue;
                float4 x = o4[(size_t)n * 350 + t];
                a.x += x.x; a.y += x.y; a.z += x.z; a.w += x.w;
            }
            a.x *= sc; a.y *= sc; a.z *= sc; a.w *= sc;
            *(uint4*)(dst + 2 * t) = splitpack4(a);
        } else {
            *(uint4*)(dst + 700 + 2 * (t - 350)) = make_uint4(0, 0, 0, 0);
        }
    }
}

__global__ void ffn_out_kernel(const float* __restrict__ h, const float* __restrict__ W2,
                               const float* __restrict__ b2, float* __restrict__ out)
{
    int m = blockIdx.x;
    float acc = 0.f;
    for (int j = threadIdx.x; j < FHD; j += 256) acc += h[m * FHD + j] * W2[j];
    __shared__ float red[256];
    red[threadIdx.x] = acc;
    __syncthreads();
    for (int st = 128; st > 0; st >>= 1) {
        if (threadIdx.x < st) red[threadIdx.x] += red[threadIdx.x + st];
        __syncthreads();
    }
    if (threadIdx.x == 0) out[m] = red[0] + b2[0];
}

// ---------------- launch ----------------
extern "C" void kernel_launch(void* const* d_in, const int* in_sizes, int n_in,
                              void* d_out, int out_size)
{
    const float* f_atoms = (const float*)d_in[0];
    const float* f_bonds = (const float*)d_in[1];
    const float* W_is    = (const float*)d_in[2];
    const float* W_iv    = (const float*)d_in[3];
    const float* W_hs    = (const float*)d_in[4];
    const float* W_hv    = (const float*)d_in[5];
    const float* W_os    = (const float*)d_in[6];
    const float* b_os    = (const float*)d_in[7];
    const float* W_ov    = (const float*)d_in[8];
    const float* b_ov    = (const float*)d_in[9];
    const float* ffn_W1  = (const float*)d_in[10];
    const float* ffn_b1  = (const float*)d_in[11];
    const float* ffn_W2  = (const float*)d_in[12];
    const float* ffn_b2  = (const float*)d_in[13];
    const int*   a2a     = (const int*)d_in[14];
    const int*   a2b     = (const int*)d_in[15];
    const int*   mol_ids = (const int*)d_in[16];
    float*       out     = (float*)d_out;

    uint2 *p_fa, *p_X, *p_sagg, *p_vagg, *p_osin, *p_ovin, *p_mol;
    uint2 *p_Wis, *p_Wiv, *p_Whs, *p_Whv, *p_Wos, *p_Wov, *p_Wff;
    float *p_si, *p_s, *p_vi, *p_v, *p_osb, *p_ovb, *p_o, *p_h;
    int* p_molstart;
    cudaGetSymbolAddress((void**)&p_fa,   g_fa_p);
    cudaGetSymbolAddress((void**)&p_X,    g_X_p);
    cudaGetSymbolAddress((void**)&p_sagg, g_sagg_p);
    cudaGetSymbolAddress((void**)&p_vagg, g_vagg_p);
    cudaGetSymbolAddress((void**)&p_osin, g_osin_p);
    cudaGetSymbolAddress((void**)&p_ovin, g_ovin_p);
    cudaGetSymbolAddress((void**)&p_mol,  g_mol_p);
    cudaGetSymbolAddress((void**)&p_Wis,  g_Wis_p);
    cudaGetSymbolAddress((void**)&p_Wiv,  g_Wiv_p);
    cudaGetSymbolAddress((void**)&p_Whs,  g_Whs_p);
    cudaGetSymbolAddress((void**)&p_Whv,  g_Whv_p);
    cudaGetSymbolAddress((void**)&p_Wos,  g_Wos_p);
    cudaGetSymbolAddress((void**)&p_Wov,  g_Wov_p);
    cudaGetSymbolAddress((void**)&p_Wff,  g_Wff_p);
    cudaGetSymbolAddress((void**)&p_si,   g_si);
    cudaGetSymbolAddress((void**)&p_s,    g_s);
    cudaGetSymbolAddress((void**)&p_vi,   g_vi);
    cudaGetSymbolAddress((void**)&p_v,    g_v);
    cudaGetSymbolAddress((void**)&p_osb,  g_osb);
    cudaGetSymbolAddress((void**)&p_ovb,  g_ovb);
    cudaGetSymbolAddress((void**)&p_o,    g_o);
    cudaGetSymbolAddress((void**)&p_h,    g_h);
    cudaGetSymbolAddress((void**)&p_molstart, g_molstart);

    cudaFuncSetAttribute(bgemm_kernel<true,false,false,true>,
                         cudaFuncAttributeMaxDynamicSharedMemorySize, SMEM_GEMM);
    cudaFuncSetAttribute(bgemm_kernel<true,true,false,false>,
                         cudaFuncAttributeMaxDynamicSharedMemorySize, SMEM_GEMM);
    cudaFuncSetAttribute(bgemm_kernel<true,false,true,false>,
                         cudaFuncAttributeMaxDynamicSharedMemorySize, SMEM_GEMM);

    const int tilesS = (NA + 127) / 128;          // 157
    const int tilesV = (3 * NA + 127) / 128;      // 469
    const int tilesM = (NM + 127) / 128;          // 7

    // 0. weight packing
    packW_kernel<<<512, 256>>>(W_is, HD, JP_FA, 0, 133, 0, 0, 0, 0, p_Wis);
    packW_kernel<<<512, 256>>>(W_iv, HD, JP_X, 0, 133, 0, 133, 133, 134, p_Wiv);
    packW_kernel<<<1024, 256>>>(W_hs, HD, JP_H, 0, 1100, 0, 0, 0, 0, p_Whs);
    packW_kernel<<<1024, 256>>>(W_hv, HD, JP_H, 0, 1100, 0, 0, 0, 0, p_Whv);
    packW_kernel<<<1024, 256>>>(W_os, FHD, JP_OS, 0, 133, 0, 133, 1100, 134, p_Wos);
    packW_kernel<<<1024, 256>>>(W_ov, FHD, JP_OV, 0, 2200, 0, 0, 0, 0, p_Wov);
    packW_kernel<<<1024, 256>>>(ffn_W1, FHD, JP_FF, 0, 1400, 0, 0, 0, 0, p_Wff);

    // 1. prep
    pack_fa_kernel<<<2048, 256>>>(f_atoms, p_fa);
    build_X_kernel<<<NA, 192>>>(f_atoms, f_bonds, a2a, a2b, p_X);

    // 2+3. si & vi fused: problem0 = fa@Wis [NA,HD], problem1 = X@Wiv [3NA,HD]
    {
        dim3 g((HD + 127) / 128, tilesS + tilesV);
        bgemm_kernel<true, false, false, true><<<g, 256, SMEM_GEMM>>>(
            p_fa, p_Wis, nullptr, nullptr, p_s, p_si, NA, 5, JP_FA,
            p_X,  p_Wiv, nullptr, nullptr, p_v, p_vi, 3 * NA, 9, JP_X,
            HD, tilesS);
    }

    // 4. message passing: s & v GEMMs fused per iteration
    for (int it = 0; it < 6; it++) {
        gather_kernel<<<NA, 256>>>(p_s, p_v, a2a, p_sagg, p_vagg);
        dim3 g((HD + 127) / 128, tilesS + tilesV);
        bgemm_kernel<true, true, false, false><<<g, 256, SMEM_GEMM>>>(
            p_sagg, p_Whs, p_si, nullptr, p_s, nullptr, NA, 35, JP_H,
            p_vagg, p_Whv, p_vi, nullptr, p_v, nullptr, 3 * NA, 35, JP_H,
            HD, tilesS);
    }

    // 5. output stage: os & ov GEMMs fused
    build_osin_kernel<<<NA, 256>>>(f_atoms, p_s, a2a, p_osin);
    build_ovin_kernel<<<NA, 256>>>(p_vi, p_v, a2a, p_ovin);
    {
        dim3 g((FHD + 127) / 128, tilesS + tilesV);
        bgemm_kernel<true, false, true, false><<<g, 256, SMEM_GEMM>>>(
            p_osin, p_Wos, nullptr, b_os, p_osb, nullptr, NA, 39, JP_OS,
            p_ovin, p_Wov, nullptr, b_ov, p_ovb, nullptr, 3 * NA, 69, JP_OV,
            FHD, tilesS);
    }
    {
        long tot3 = (long)NA * 350;
        build_o_kernel<<<(unsigned)((tot3 + 255) / 256), 256>>>(p_osb, p_ovb, p_o);
    }

    // 6. readout + FFN (single problem: duplicate descriptor)
    mol_start_kernel<<<4, 256>>>(mol_ids, p_molstart);
    segment_mean_kernel<<<NM, 256>>>(p_o, p_molstart, p_mol);
    {
        dim3 g((FHD + 127) / 128, tilesM);
        bgemm_kernel<true, false, true, false><<<g, 256, SMEM_GEMM>>>(
            p_mol, p_Wff, nullptr, ffn_b1, p_h, nullptr, NM, 44, JP_FF,
            p_mol, p_Wff, nullptr, ffn_b1, p_h, nullptr, NM, 44, JP_FF,
            FHD, tilesM);
    }
    ffn_out_kernel<<<NM, 256>>>(p_h, ffn_W2, ffn_b2, out);
}